// round 1
// baseline (speedup 1.0000x reference)
#include <cuda_runtime.h>
#include <math.h>

// Problem constants
static constexpr int BB  = 4;
static constexpr int TT  = 4096;
static constexpr int DD  = 1024;
static constexpr int HH  = 16;
static constexpr int DKK = 64;
static constexpr int MT  = BB * TT;      // 16384 tokens
#define EPSV 1e-6f

// Scratch (device globals — no allocation allowed)
__device__ float g_q[MT * DD];
__device__ float g_k[MT * DD];
__device__ float g_v[MT * DD];
__device__ float g_attn[MT * DD];
__device__ float g_kv[BB * HH * DKK * DKK];
__device__ float g_ksum[BB * HH * DKK];

__device__ __forceinline__ float phi_act(float x) {
    // elu(x)+1 : x>0 ? x+1 : exp(x)
    return x > 0.0f ? x + 1.0f : expf(x);
}

// ---------------------------------------------------------------------------
// SGEMM: C[M,N] = A[M,K] @ W[N,K]^T + bias[N], optional phi activation.
// 128x128 tile, BK=8, 256 threads, 8x8 micro-tile per thread.
// Assumes M%128==0, N%128==0, K%8==0.
// ---------------------------------------------------------------------------
template <int ACT>
__global__ __launch_bounds__(256) void sgemm_bias_act(
    const float* __restrict__ A, const float* __restrict__ W,
    const float* __restrict__ bias, float* __restrict__ C,
    int M, int N, int K)
{
    __shared__ float As[8][128];
    __shared__ float Bs[8][128];

    const int tid  = threadIdx.x;
    const int bm   = blockIdx.y;
    const int bn   = blockIdx.x;
    const int lrow = tid >> 1;            // 0..127
    const int lcol = (tid & 1) * 4;       // 0 or 4
    const int tx   = tid & 15;            // n micro-tile
    const int ty   = tid >> 4;            // m micro-tile

    const float* Ag = A + (size_t)(bm * 128 + lrow) * K + lcol;
    const float* Wg = W + (size_t)(bn * 128 + lrow) * K + lcol;

    float acc[8][8];
    #pragma unroll
    for (int i = 0; i < 8; i++)
        #pragma unroll
        for (int j = 0; j < 8; j++) acc[i][j] = 0.0f;

    for (int k0 = 0; k0 < K; k0 += 8) {
        float4 av = *(const float4*)(Ag + k0);
        float4 wv = *(const float4*)(Wg + k0);
        As[lcol + 0][lrow] = av.x; As[lcol + 1][lrow] = av.y;
        As[lcol + 2][lrow] = av.z; As[lcol + 3][lrow] = av.w;
        Bs[lcol + 0][lrow] = wv.x; Bs[lcol + 1][lrow] = wv.y;
        Bs[lcol + 2][lrow] = wv.z; Bs[lcol + 3][lrow] = wv.w;
        __syncthreads();

        #pragma unroll
        for (int kk = 0; kk < 8; kk++) {
            float a[8], b[8];
            *(float4*)&a[0] = *(const float4*)&As[kk][ty * 8];
            *(float4*)&a[4] = *(const float4*)&As[kk][ty * 8 + 4];
            *(float4*)&b[0] = *(const float4*)&Bs[kk][tx * 8];
            *(float4*)&b[4] = *(const float4*)&Bs[kk][tx * 8 + 4];
            #pragma unroll
            for (int i = 0; i < 8; i++)
                #pragma unroll
                for (int j = 0; j < 8; j++)
                    acc[i][j] = fmaf(a[i], b[j], acc[i][j]);
        }
        __syncthreads();
    }

    // Epilogue: bias + optional activation, float4 stores.
    #pragma unroll
    for (int i = 0; i < 8; i++) {
        const int m = bm * 128 + ty * 8 + i;
        #pragma unroll
        for (int j = 0; j < 8; j += 4) {
            const int n = bn * 128 + tx * 8 + j;
            float4 o;
            o.x = acc[i][j + 0] + bias[n + 0];
            o.y = acc[i][j + 1] + bias[n + 1];
            o.z = acc[i][j + 2] + bias[n + 2];
            o.w = acc[i][j + 3] + bias[n + 3];
            if (ACT) {
                o.x = phi_act(o.x); o.y = phi_act(o.y);
                o.z = phi_act(o.z); o.w = phi_act(o.w);
            }
            *(float4*)(C + (size_t)m * N + n) = o;
        }
    }
}

// ---------------------------------------------------------------------------
// KV summary: per (b,h): kv[dk,dm] += sum_t k[t,dk]*v[t,dm]; ksum[dk] += sum_t k[t,dk]
// grid: (B*H, 8 T-splits), 256 threads, 4x4 micro-tile, atomic reduce.
// ---------------------------------------------------------------------------
__global__ __launch_bounds__(256) void kv_kernel(
    const float* __restrict__ k, const float* __restrict__ v)
{
    const int bh = blockIdx.x;
    const int b  = bh >> 4;
    const int h  = bh & 15;
    const size_t base = (size_t)b * TT * DD + (size_t)h * DKK;
    const int t0 = blockIdx.y * 512;

    __shared__ float ks[16][64];
    __shared__ float vs[16][64];

    const int tid = threadIdx.x;
    const int r   = tid >> 4;
    const int c   = (tid & 15) * 4;
    const int tx  = tid & 15;
    const int ty  = tid >> 4;

    float acc[4][4];
    #pragma unroll
    for (int i = 0; i < 4; i++)
        #pragma unroll
        for (int j = 0; j < 4; j++) acc[i][j] = 0.0f;
    float ksacc = 0.0f;

    for (int tc = 0; tc < 512; tc += 16) {
        const size_t off = base + (size_t)(t0 + tc + r) * DD + c;
        float4 kf = *(const float4*)(k + off);
        float4 vf = *(const float4*)(v + off);
        *(float4*)&ks[r][c] = kf;
        *(float4*)&vs[r][c] = vf;
        __syncthreads();

        #pragma unroll
        for (int tt = 0; tt < 16; tt++) {
            float a[4], bb[4];
            *(float4*)a  = *(const float4*)&ks[tt][ty * 4];
            *(float4*)bb = *(const float4*)&vs[tt][tx * 4];
            #pragma unroll
            for (int i = 0; i < 4; i++)
                #pragma unroll
                for (int j = 0; j < 4; j++)
                    acc[i][j] = fmaf(a[i], bb[j], acc[i][j]);
        }
        if (tid < 64) {
            #pragma unroll
            for (int tt = 0; tt < 16; tt++) ksacc += ks[tt][tid];
        }
        __syncthreads();
    }

    float* kvb = g_kv + (size_t)bh * DKK * DKK;
    #pragma unroll
    for (int i = 0; i < 4; i++)
        #pragma unroll
        for (int j = 0; j < 4; j++)
            atomicAdd(&kvb[(ty * 4 + i) * DKK + tx * 4 + j], acc[i][j]);
    if (tid < 64) atomicAdd(&g_ksum[bh * DKK + tid], ksacc);
}

// ---------------------------------------------------------------------------
// Attention apply: out[t,dm] = z[t] * sum_dk q[t,dk]*kv[dk,dm]
// z[t] = 1/(q[t]·(ksum+eps) + eps). grid: (B*H, T/128), 256 threads.
// ---------------------------------------------------------------------------
__global__ __launch_bounds__(256) void attn_kernel(const float* __restrict__ q)
{
    const int bh = blockIdx.x;
    const int b  = bh >> 4;
    const int h  = bh & 15;
    const int t0 = blockIdx.y * 128;

    __shared__ float kvs[64][64];   // 16 KB
    __shared__ float qs[128][64];   // 32 KB
    __shared__ float zs[128];
    __shared__ float kse[64];

    const int tid = threadIdx.x;

    // load kv tile (4096 floats)
    {
        const float4* src = (const float4*)(g_kv + (size_t)bh * DKK * DKK);
        float4* dst = (float4*)&kvs[0][0];
        #pragma unroll
        for (int i = 0; i < 4; i++)
            dst[i * 256 + tid] = src[i * 256 + tid];
    }
    // load q tile (128 x 64)
    #pragma unroll
    for (int i = 0; i < 8; i++) {
        const int f  = i * 256 + tid;
        const int tr = f >> 4;
        const int cc = (f & 15) * 4;
        *(float4*)&qs[tr][cc] =
            *(const float4*)(q + (size_t)(b * TT + t0 + tr) * DD + h * DKK + cc);
    }
    if (tid < 64) kse[tid] = g_ksum[bh * DKK + tid] + EPSV;
    __syncthreads();

    if (tid < 128) {
        float s = EPSV;
        #pragma unroll
        for (int d = 0; d < 64; d++) s = fmaf(qs[tid][d], kse[d], s);
        zs[tid] = 1.0f / s;
    }
    __syncthreads();

    const int tx = tid & 15;   // dm group (4 cols)
    const int ty = tid >> 4;   // t group  (8 rows)
    float acc[8][4];
    #pragma unroll
    for (int i = 0; i < 8; i++)
        #pragma unroll
        for (int j = 0; j < 4; j++) acc[i][j] = 0.0f;

    for (int d = 0; d < 64; d++) {
        float bb[4];
        *(float4*)bb = *(const float4*)&kvs[d][tx * 4];
        #pragma unroll
        for (int i = 0; i < 8; i++) {
            const float a = qs[ty * 8 + i][d];
            #pragma unroll
            for (int j = 0; j < 4; j++)
                acc[i][j] = fmaf(a, bb[j], acc[i][j]);
        }
    }

    #pragma unroll
    for (int i = 0; i < 8; i++) {
        const int t = t0 + ty * 8 + i;
        const float z = zs[ty * 8 + i];
        float4 o;
        o.x = acc[i][0] * z; o.y = acc[i][1] * z;
        o.z = acc[i][2] * z; o.w = acc[i][3] * z;
        *(float4*)(g_attn + (size_t)(b * TT + t) * DD + h * DKK + tx * 4) = o;
    }
}

// ---------------------------------------------------------------------------
extern "C" void kernel_launch(void* const* d_in, const int* in_sizes, int n_in,
                              void* d_out, int out_size)
{
    const float* x  = (const float*)d_in[0];
    const float* Wq = (const float*)d_in[1];
    const float* bq = (const float*)d_in[2];
    const float* Wk = (const float*)d_in[3];
    const float* bk = (const float*)d_in[4];
    const float* Wv = (const float*)d_in[5];
    const float* bv = (const float*)d_in[6];
    const float* Wo = (const float*)d_in[7];
    const float* bo = (const float*)d_in[8];
    float* out = (float*)d_out;

    float *qp, *kp, *vp, *ap, *kvp, *ksp;
    cudaGetSymbolAddress((void**)&qp,  g_q);
    cudaGetSymbolAddress((void**)&kp,  g_k);
    cudaGetSymbolAddress((void**)&vp,  g_v);
    cudaGetSymbolAddress((void**)&ap,  g_attn);
    cudaGetSymbolAddress((void**)&kvp, g_kv);
    cudaGetSymbolAddress((void**)&ksp, g_ksum);

    dim3 gg(DD / 128, MT / 128);   // (8, 128)

    sgemm_bias_act<1><<<gg, 256>>>(x, Wq, bq, qp, MT, DD, DD);
    sgemm_bias_act<1><<<gg, 256>>>(x, Wk, bk, kp, MT, DD, DD);
    sgemm_bias_act<0><<<gg, 256>>>(x, Wv, bv, vp, MT, DD, DD);

    cudaMemsetAsync(kvp, 0, sizeof(float) * BB * HH * DKK * DKK);
    cudaMemsetAsync(ksp, 0, sizeof(float) * BB * HH * DKK);

    kv_kernel<<<dim3(BB * HH, 8), 256>>>(kp, vp);
    attn_kernel<<<dim3(BB * HH, TT / 128), 256>>>(qp);

    sgemm_bias_act<0><<<gg, 256>>>(ap, Wo, bo, out, MT, DD, DD);
}

// round 4
// speedup vs baseline: 2.0054x; 2.0054x over previous
#include <cuda_runtime.h>
#include <cuda_bf16.h>
#include <math.h>
#include <stdint.h>

// Problem constants
static constexpr int BB  = 4;
static constexpr int TT  = 4096;
static constexpr int DD  = 1024;
static constexpr int HH  = 16;
static constexpr int DKK = 64;
static constexpr int MT  = BB * TT;      // 16384 tokens
static constexpr int K2  = 3 * DD;       // three-term split-bf16 K = 3072
static constexpr int BKC = 32;           // K-chunk (bf16 elems)
static constexpr int NCHUNK = K2 / BKC;  // 96
#define EPSV 1e-6f

// SMEM geometry: rows padded to 40 bf16 (80 B) for conflict-free ldmatrix
static constexpr int ROWB  = 80;
static constexpr int TILEB = 128 * ROWB;     // 10240 B per operand tile
static constexpr int STGB  = 2 * TILEB;      // A+B per stage
static constexpr int NSTG  = 4;
static constexpr int SMEM_GEMM = NSTG * STGB; // 81920 B

// ---------------------------------------------------------------------------
// Scratch (device globals — no allocation allowed)
// ---------------------------------------------------------------------------
__device__ __nv_bfloat16 g_xs[(size_t)MT * K2];   // x split     (96 MB)
__device__ __nv_bfloat16 g_as[(size_t)MT * K2];   // attn split  (96 MB)
__device__ __nv_bfloat16 g_wqs[DD * K2];
__device__ __nv_bfloat16 g_wks[DD * K2];
__device__ __nv_bfloat16 g_wvs[DD * K2];
__device__ __nv_bfloat16 g_wos[DD * K2];
__device__ float g_q[(size_t)MT * DD];
__device__ float g_k[(size_t)MT * DD];
__device__ float g_v[(size_t)MT * DD];
__device__ float g_attn[(size_t)MT * DD];
__device__ float g_kv[BB * HH * DKK * DKK];
__device__ float g_ksum[BB * HH * DKK];

__device__ __forceinline__ float phi_act(float x) {
    return x > 0.0f ? x + 1.0f : expf(x);
}

// ---------------------------------------------------------------------------
// PTX helpers (baseline sm_80+ features only — target is sm_103, no 'a' ISA)
// ---------------------------------------------------------------------------
__device__ __forceinline__ uint32_t smem_u32(const void* p) {
    uint32_t a;
    asm("{ .reg .u64 t; cvta.to.shared.u64 t, %1; cvt.u32.u64 %0, t; }"
        : "=r"(a) : "l"(p));
    return a;
}

#define CP_ASYNC16(sm, gp) \
    asm volatile("cp.async.cg.shared.global [%0], [%1], 16;" :: "r"(sm), "l"(gp))
#define CP_COMMIT() asm volatile("cp.async.commit_group;")
template <int N> __device__ __forceinline__ void cp_wait() {
    asm volatile("cp.async.wait_group %0;" :: "n"(N));
}

__device__ __forceinline__ void ldsm_x4(uint32_t* r, uint32_t addr) {
    asm volatile("ldmatrix.sync.aligned.m8n8.x4.shared.b16 {%0,%1,%2,%3}, [%4];"
                 : "=r"(r[0]), "=r"(r[1]), "=r"(r[2]), "=r"(r[3]) : "r"(addr));
}

__device__ __forceinline__ void mma_bf16(float* c, const uint32_t* a,
                                         uint32_t b0, uint32_t b1) {
    asm volatile(
        "mma.sync.aligned.m16n8k16.row.col.f32.bf16.bf16.f32 "
        "{%0,%1,%2,%3}, {%4,%5,%6,%7}, {%8,%9}, {%0,%1,%2,%3};"
        : "+f"(c[0]), "+f"(c[1]), "+f"(c[2]), "+f"(c[3])
        : "r"(a[0]), "r"(a[1]), "r"(a[2]), "r"(a[3]), "r"(b0), "r"(b1));
}

// ---------------------------------------------------------------------------
// Tensor-core GEMM (HMMA): C[M,1024] = A[M,K2]@W[1024,K2]^T + bias (+phi)
// CTA 128x128, BK=32, 8 warps (2x4), warp tile 64x32, 4-stage cp.async.
// ---------------------------------------------------------------------------
template <int ACT>
__global__ void __launch_bounds__(256, 2) gemm_bf16(
    const __nv_bfloat16* __restrict__ A, const __nv_bfloat16* __restrict__ W,
    const float* __restrict__ bias, float* __restrict__ C)
{
    extern __shared__ char smraw[];
    const uint32_t tiles = smem_u32(smraw);
    const int tid  = threadIdx.x;
    const int wid  = tid >> 5, lane = tid & 31;
    const int wm   = wid >> 2;            // 0..1  (M)
    const int wn   = wid & 3;             // 0..3  (N)
    const int bm   = blockIdx.y, bn = blockIdx.x;

    // ---- load geometry: each thread copies 2x16B per operand per chunk ----
    const int lrow = tid >> 1;             // 0..127
    const int lc16 = (tid & 1) * 2;        // 16B-segment pair {0,1} or {2,3}
    const uint32_t sw0 = (uint32_t)lrow * ROWB + lc16 * 16;
    const char* Ag = (const char*)(A + (size_t)(bm * 128 + lrow) * K2) + lc16 * 16;
    const char* Wg = (const char*)(W + (size_t)(bn * 128 + lrow) * K2) + lc16 * 16;

    auto load_chunk = [&](int kc) {
        const uint32_t st = tiles + (kc & (NSTG - 1)) * STGB;
        const char* ga = Ag + (size_t)kc * (BKC * 2);
        const char* gb = Wg + (size_t)kc * (BKC * 2);
        CP_ASYNC16(st + sw0,               ga);
        CP_ASYNC16(st + sw0 + 16,          ga + 16);
        CP_ASYNC16(st + TILEB + sw0,       gb);
        CP_ASYNC16(st + TILEB + sw0 + 16,  gb + 16);
        CP_COMMIT();
    };

    // ---- ldmatrix geometry ----
    const uint32_t a_off =
        (uint32_t)(wm * 64 + (lane & 15)) * ROWB + (lane >> 4) * 16;
    const uint32_t b_off =
        TILEB + (uint32_t)(wn * 32 + (lane & 15)) * ROWB + (lane >> 4) * 16;

    float acc[4][4][4];
    #pragma unroll
    for (int i = 0; i < 4; i++)
        #pragma unroll
        for (int j = 0; j < 4; j++)
            #pragma unroll
            for (int r = 0; r < 4; r++) acc[i][j][r] = 0.0f;

    load_chunk(0); load_chunk(1); load_chunk(2);

    #pragma unroll 1
    for (int kc = 0; kc < NCHUNK; kc++) {
        if (kc < NCHUNK - 2)       cp_wait<2>();
        else if (kc == NCHUNK - 2) cp_wait<1>();
        else                       cp_wait<0>();
        __syncthreads();

        // prefetch chunk kc+3 (its stage was last read at iter kc-1; the
        // barrier above orders those reads before these writes)
        if (kc + 3 < NCHUNK) load_chunk(kc + 3);

        const uint32_t st = tiles + (kc & (NSTG - 1)) * STGB;
        #pragma unroll
        for (int ks = 0; ks < 2; ks++) {
            const uint32_t kb = ks * 32;  // 16 bf16 = 32 B
            uint32_t a[4][4], b[2][4];
            #pragma unroll
            for (int mf = 0; mf < 4; mf++)
                ldsm_x4(a[mf], st + a_off + mf * (16 * ROWB) + kb);
            #pragma unroll
            for (int nf2 = 0; nf2 < 2; nf2++)
                ldsm_x4(b[nf2], st + b_off + nf2 * (16 * ROWB) + kb);
            #pragma unroll
            for (int mf = 0; mf < 4; mf++) {
                #pragma unroll
                for (int nf = 0; nf < 4; nf++)
                    mma_bf16(acc[mf][nf], a[mf],
                             b[nf >> 1][nf & 1], b[nf >> 1][(nf & 1) + 2]);
            }
        }
    }

    // ---- epilogue: bias (+phi), fp32 stores ----
    #pragma unroll
    for (int mf = 0; mf < 4; mf++) {
        const int m0 = bm * 128 + wm * 64 + mf * 16 + (lane >> 2);
        #pragma unroll
        for (int nf = 0; nf < 4; nf++) {
            const int nc = bn * 128 + wn * 32 + nf * 8 + (lane & 3) * 2;
            const float b0 = __ldg(bias + nc), b1 = __ldg(bias + nc + 1);
            float2 lo, hi;
            lo.x = acc[mf][nf][0] + b0; lo.y = acc[mf][nf][1] + b1;
            hi.x = acc[mf][nf][2] + b0; hi.y = acc[mf][nf][3] + b1;
            if (ACT) {
                lo.x = phi_act(lo.x); lo.y = phi_act(lo.y);
                hi.x = phi_act(hi.x); hi.y = phi_act(hi.y);
            }
            *(float2*)(C + (size_t)m0 * 1024 + nc)       = lo;
            *(float2*)(C + (size_t)(m0 + 8) * 1024 + nc) = hi;
        }
    }
}

// ---------------------------------------------------------------------------
// fp32 -> three-term split-bf16 [rows, 1024] -> [rows, 3072]
// MODE 0 (activation): [hi | lo | hi]
// MODE 1 (weight):     [hi | hi | lo]
// so A_cat·W_cat = A_hi·W_hi + A_lo·W_hi + A_hi·W_lo  (lo·lo dropped, ~4e-6)
// ---------------------------------------------------------------------------
template <int MODE>
__global__ __launch_bounds__(256) void split_bf16(
    const float* __restrict__ src, __nv_bfloat16* __restrict__ dst)
{
    const int m = blockIdx.x;
    const int c = threadIdx.x * 4;
    float4 v = *(const float4*)(src + (size_t)m * 1024 + c);
    __nv_bfloat16 h0 = __float2bfloat16(v.x), h1 = __float2bfloat16(v.y);
    __nv_bfloat16 h2 = __float2bfloat16(v.z), h3 = __float2bfloat16(v.w);
    __nv_bfloat16 l0 = __float2bfloat16(v.x - __bfloat162float(h0));
    __nv_bfloat16 l1 = __float2bfloat16(v.y - __bfloat162float(h1));
    __nv_bfloat16 l2 = __float2bfloat16(v.z - __bfloat162float(h2));
    __nv_bfloat16 l3 = __float2bfloat16(v.w - __bfloat162float(h3));
    __nv_bfloat162 hA(h0, h1), hB(h2, h3), lA(l0, l1), lB(l2, l3);
    __nv_bfloat16* row = dst + (size_t)m * (size_t)K2;
    __nv_bfloat162* d0 = (__nv_bfloat162*)(row + c);          // seg0: hi
    __nv_bfloat162* d1 = (__nv_bfloat162*)(row + 1024 + c);   // seg1
    __nv_bfloat162* d2 = (__nv_bfloat162*)(row + 2048 + c);   // seg2
    d0[0] = hA; d0[1] = hB;
    if (MODE == 0) {  // activation: [hi | lo | hi]
        d1[0] = lA; d1[1] = lB;
        d2[0] = hA; d2[1] = hB;
    } else {          // weight: [hi | hi | lo]
        d1[0] = hA; d1[1] = hB;
        d2[0] = lA; d2[1] = lB;
    }
}

// ---------------------------------------------------------------------------
// KV summary
// ---------------------------------------------------------------------------
__global__ __launch_bounds__(256) void kv_kernel(
    const float* __restrict__ k, const float* __restrict__ v)
{
    const int bh = blockIdx.x;
    const int b  = bh >> 4;
    const int h  = bh & 15;
    const size_t base = (size_t)b * TT * DD + (size_t)h * DKK;
    const int t0 = blockIdx.y * 512;

    __shared__ float ks[16][64];
    __shared__ float vs[16][64];

    const int tid = threadIdx.x;
    const int r   = tid >> 4;
    const int c   = (tid & 15) * 4;
    const int tx  = tid & 15;
    const int ty  = tid >> 4;

    float acc[4][4];
    #pragma unroll
    for (int i = 0; i < 4; i++)
        #pragma unroll
        for (int j = 0; j < 4; j++) acc[i][j] = 0.0f;
    float ksacc = 0.0f;

    for (int tc = 0; tc < 512; tc += 16) {
        const size_t off = base + (size_t)(t0 + tc + r) * DD + c;
        *(float4*)&ks[r][c] = *(const float4*)(k + off);
        *(float4*)&vs[r][c] = *(const float4*)(v + off);
        __syncthreads();
        #pragma unroll
        for (int tt = 0; tt < 16; tt++) {
            float a[4], bb[4];
            *(float4*)a  = *(const float4*)&ks[tt][ty * 4];
            *(float4*)bb = *(const float4*)&vs[tt][tx * 4];
            #pragma unroll
            for (int i = 0; i < 4; i++)
                #pragma unroll
                for (int j = 0; j < 4; j++)
                    acc[i][j] = fmaf(a[i], bb[j], acc[i][j]);
        }
        if (tid < 64) {
            #pragma unroll
            for (int tt = 0; tt < 16; tt++) ksacc += ks[tt][tid];
        }
        __syncthreads();
    }

    float* kvb = g_kv + (size_t)bh * DKK * DKK;
    #pragma unroll
    for (int i = 0; i < 4; i++)
        #pragma unroll
        for (int j = 0; j < 4; j++)
            atomicAdd(&kvb[(ty * 4 + i) * DKK + tx * 4 + j], acc[i][j]);
    if (tid < 64) atomicAdd(&g_ksum[bh * DKK + tid], ksacc);
}

// ---------------------------------------------------------------------------
// Attention apply
// ---------------------------------------------------------------------------
__global__ __launch_bounds__(256) void attn_kernel(const float* __restrict__ q)
{
    const int bh = blockIdx.x;
    const int b  = bh >> 4;
    const int h  = bh & 15;
    const int t0 = blockIdx.y * 128;

    __shared__ float kvs[64][64];
    __shared__ float qs[128][64];
    __shared__ float zs[128];
    __shared__ float kse[64];

    const int tid = threadIdx.x;
    {
        const float4* src = (const float4*)(g_kv + (size_t)bh * DKK * DKK);
        float4* dst = (float4*)&kvs[0][0];
        #pragma unroll
        for (int i = 0; i < 4; i++) dst[i * 256 + tid] = src[i * 256 + tid];
    }
    #pragma unroll
    for (int i = 0; i < 8; i++) {
        const int f  = i * 256 + tid;
        const int tr = f >> 4;
        const int cc = (f & 15) * 4;
        *(float4*)&qs[tr][cc] =
            *(const float4*)(q + (size_t)(b * TT + t0 + tr) * DD + h * DKK + cc);
    }
    if (tid < 64) kse[tid] = g_ksum[bh * DKK + tid] + EPSV;
    __syncthreads();

    if (tid < 128) {
        float s = EPSV;
        #pragma unroll
        for (int d = 0; d < 64; d++) s = fmaf(qs[tid][d], kse[d], s);
        zs[tid] = 1.0f / s;
    }
    __syncthreads();

    const int tx = tid & 15;
    const int ty = tid >> 4;
    float acc[8][4];
    #pragma unroll
    for (int i = 0; i < 8; i++)
        #pragma unroll
        for (int j = 0; j < 4; j++) acc[i][j] = 0.0f;

    for (int d = 0; d < 64; d++) {
        float bb[4];
        *(float4*)bb = *(const float4*)&kvs[d][tx * 4];
        #pragma unroll
        for (int i = 0; i < 8; i++) {
            const float a = qs[ty * 8 + i][d];
            #pragma unroll
            for (int j = 0; j < 4; j++)
                acc[i][j] = fmaf(a, bb[j], acc[i][j]);
        }
    }

    #pragma unroll
    for (int i = 0; i < 8; i++) {
        const int t = t0 + ty * 8 + i;
        const float z = zs[ty * 8 + i];
        float4 o;
        o.x = acc[i][0] * z; o.y = acc[i][1] * z;
        o.z = acc[i][2] * z; o.w = acc[i][3] * z;
        *(float4*)(g_attn + (size_t)(b * TT + t) * DD + h * DKK + tx * 4) = o;
    }
}

// ---------------------------------------------------------------------------
extern "C" void kernel_launch(void* const* d_in, const int* in_sizes, int n_in,
                              void* d_out, int out_size)
{
    const float* x  = (const float*)d_in[0];
    const float* Wq = (const float*)d_in[1];
    const float* bq = (const float*)d_in[2];
    const float* Wk = (const float*)d_in[3];
    const float* bk = (const float*)d_in[4];
    const float* Wv = (const float*)d_in[5];
    const float* bv = (const float*)d_in[6];
    const float* Wo = (const float*)d_in[7];
    const float* bo = (const float*)d_in[8];
    float* out = (float*)d_out;

    __nv_bfloat16 *xs, *as, *wqs, *wks, *wvs, *wos;
    float *qp, *kp, *vp, *ap, *kvp, *ksp;
    cudaGetSymbolAddress((void**)&xs,  g_xs);
    cudaGetSymbolAddress((void**)&as,  g_as);
    cudaGetSymbolAddress((void**)&wqs, g_wqs);
    cudaGetSymbolAddress((void**)&wks, g_wks);
    cudaGetSymbolAddress((void**)&wvs, g_wvs);
    cudaGetSymbolAddress((void**)&wos, g_wos);
    cudaGetSymbolAddress((void**)&qp,  g_q);
    cudaGetSymbolAddress((void**)&kp,  g_k);
    cudaGetSymbolAddress((void**)&vp,  g_v);
    cudaGetSymbolAddress((void**)&ap,  g_attn);
    cudaGetSymbolAddress((void**)&kvp, g_kv);
    cudaGetSymbolAddress((void**)&ksp, g_ksum);

    cudaFuncSetAttribute(gemm_bf16<0>, cudaFuncAttributeMaxDynamicSharedMemorySize, SMEM_GEMM);
    cudaFuncSetAttribute(gemm_bf16<1>, cudaFuncAttributeMaxDynamicSharedMemorySize, SMEM_GEMM);

    // split-bf16 conversions
    split_bf16<0><<<MT, 256>>>(x, xs);
    split_bf16<1><<<DD, 256>>>(Wq, wqs);
    split_bf16<1><<<DD, 256>>>(Wk, wks);
    split_bf16<1><<<DD, 256>>>(Wv, wvs);
    split_bf16<1><<<DD, 256>>>(Wo, wos);

    dim3 gg(DD / 128, MT / 128);   // (8, 128)
    gemm_bf16<1><<<gg, 256, SMEM_GEMM>>>(xs, wqs, bq, qp);
    gemm_bf16<1><<<gg, 256, SMEM_GEMM>>>(xs, wks, bk, kp);
    gemm_bf16<0><<<gg, 256, SMEM_GEMM>>>(xs, wvs, bv, vp);

    cudaMemsetAsync(kvp, 0, sizeof(float) * BB * HH * DKK * DKK);
    cudaMemsetAsync(ksp, 0, sizeof(float) * BB * HH * DKK);

    kv_kernel<<<dim3(BB * HH, 8), 256>>>(kp, vp);
    attn_kernel<<<dim3(BB * HH, TT / 128), 256>>>(qp);

    split_bf16<0><<<MT, 256>>>(ap, as);
    gemm_bf16<0><<<gg, 256, SMEM_GEMM>>>(as, wos, bo, out);
}

// round 5
// speedup vs baseline: 2.8414x; 1.4169x over previous
#include <cuda_runtime.h>
#include <cuda_fp16.h>
#include <math.h>
#include <stdint.h>

// Problem constants
static constexpr int BB  = 4;
static constexpr int TT  = 4096;
static constexpr int DD  = 1024;
static constexpr int HH  = 16;
static constexpr int DKK = 64;
static constexpr int MT  = BB * TT;      // 16384 tokens
static constexpr int K2  = 2 * DD;       // two-term fp16 split K = 2048
static constexpr int BKC = 32;           // K-chunk (fp16 elems)
static constexpr int NCHUNK = K2 / BKC;  // 64
#define EPSV 1e-6f

// SMEM geometry: rows padded to 40 fp16 (80 B) for conflict-free ldmatrix
static constexpr int ROWB  = 80;
static constexpr int TILEB = 128 * ROWB;     // 10240 B per operand tile
static constexpr int STGB  = 2 * TILEB;      // A+B per stage
static constexpr int NSTG  = 4;
static constexpr int SMEM_GEMM = NSTG * STGB; // 81920 B

// ---------------------------------------------------------------------------
// Scratch (device globals — no allocation allowed)
// ---------------------------------------------------------------------------
__device__ __half g_xs[(size_t)MT * K2];   // x split     (64 MB)
__device__ __half g_as[(size_t)MT * K2];   // attn split  (64 MB)
__device__ __half g_wqs[DD * K2];
__device__ __half g_wks[DD * K2];
__device__ __half g_wvs[DD * K2];
__device__ __half g_wos[DD * K2];
__device__ float g_q[(size_t)MT * DD];
__device__ float g_k[(size_t)MT * DD];
__device__ float g_v[(size_t)MT * DD];
__device__ float g_attn[(size_t)MT * DD];
__device__ float g_kv[BB * HH * DKK * DKK];
__device__ float g_ksum[BB * HH * DKK];

__device__ __forceinline__ float phi_act(float x) {
    return x > 0.0f ? x + 1.0f : expf(x);
}

// ---------------------------------------------------------------------------
// PTX helpers (baseline sm_80+ features only — target is sm_103, no 'a' ISA)
// ---------------------------------------------------------------------------
__device__ __forceinline__ uint32_t smem_u32(const void* p) {
    uint32_t a;
    asm("{ .reg .u64 t; cvta.to.shared.u64 t, %1; cvt.u32.u64 %0, t; }"
        : "=r"(a) : "l"(p));
    return a;
}

#define CP_ASYNC16(sm, gp) \
    asm volatile("cp.async.cg.shared.global [%0], [%1], 16;" :: "r"(sm), "l"(gp))
#define CP_COMMIT() asm volatile("cp.async.commit_group;")
template <int N> __device__ __forceinline__ void cp_wait() {
    asm volatile("cp.async.wait_group %0;" :: "n"(N));
}

__device__ __forceinline__ void ldsm_x4(uint32_t* r, uint32_t addr) {
    asm volatile("ldmatrix.sync.aligned.m8n8.x4.shared.b16 {%0,%1,%2,%3}, [%4];"
                 : "=r"(r[0]), "=r"(r[1]), "=r"(r[2]), "=r"(r[3]) : "r"(addr));
}

__device__ __forceinline__ void mma_fp16(float* c, const uint32_t* a,
                                         uint32_t b0, uint32_t b1) {
    asm volatile(
        "mma.sync.aligned.m16n8k16.row.col.f32.f16.f16.f32 "
        "{%0,%1,%2,%3}, {%4,%5,%6,%7}, {%8,%9}, {%0,%1,%2,%3};"
        : "+f"(c[0]), "+f"(c[1]), "+f"(c[2]), "+f"(c[3])
        : "r"(a[0]), "r"(a[1]), "r"(a[2]), "r"(a[3]), "r"(b0), "r"(b1));
}

// ---------------------------------------------------------------------------
// Tensor-core GEMM (HMMA): C[M,1024] = A[M,K2]@W[1024,K2]^T + bias (+phi)
// CTA 128x128, BK=32, 8 warps (2x4), warp tile 64x32, 4-stage cp.async.
// ---------------------------------------------------------------------------
template <int ACT>
__global__ void __launch_bounds__(256, 2) gemm_fp16(
    const __half* __restrict__ A, const __half* __restrict__ W,
    const float* __restrict__ bias, float* __restrict__ C)
{
    extern __shared__ char smraw[];
    const uint32_t tiles = smem_u32(smraw);
    const int tid  = threadIdx.x;
    const int wid  = tid >> 5, lane = tid & 31;
    const int wm   = wid >> 2;            // 0..1  (M)
    const int wn   = wid & 3;             // 0..3  (N)
    const int bm   = blockIdx.y, bn = blockIdx.x;

    // ---- load geometry: each thread copies 2x16B per operand per chunk ----
    const int lrow = tid >> 1;             // 0..127
    const int lc16 = (tid & 1) * 2;        // 16B-segment pair {0,1} or {2,3}
    const uint32_t sw0 = (uint32_t)lrow * ROWB + lc16 * 16;
    const char* Ag = (const char*)(A + (size_t)(bm * 128 + lrow) * K2) + lc16 * 16;
    const char* Wg = (const char*)(W + (size_t)(bn * 128 + lrow) * K2) + lc16 * 16;

    auto load_chunk = [&](int kc) {
        const uint32_t st = tiles + (kc & (NSTG - 1)) * STGB;
        const char* ga = Ag + (size_t)kc * (BKC * 2);
        const char* gb = Wg + (size_t)kc * (BKC * 2);
        CP_ASYNC16(st + sw0,               ga);
        CP_ASYNC16(st + sw0 + 16,          ga + 16);
        CP_ASYNC16(st + TILEB + sw0,       gb);
        CP_ASYNC16(st + TILEB + sw0 + 16,  gb + 16);
        CP_COMMIT();
    };

    // ---- ldmatrix geometry ----
    const uint32_t a_off =
        (uint32_t)(wm * 64 + (lane & 15)) * ROWB + (lane >> 4) * 16;
    const uint32_t b_off =
        TILEB + (uint32_t)(wn * 32 + (lane & 15)) * ROWB + (lane >> 4) * 16;

    float acc[4][4][4];
    #pragma unroll
    for (int i = 0; i < 4; i++)
        #pragma unroll
        for (int j = 0; j < 4; j++)
            #pragma unroll
            for (int r = 0; r < 4; r++) acc[i][j][r] = 0.0f;

    load_chunk(0); load_chunk(1); load_chunk(2);

    #pragma unroll 1
    for (int kc = 0; kc < NCHUNK; kc++) {
        if (kc < NCHUNK - 2)       cp_wait<2>();
        else if (kc == NCHUNK - 2) cp_wait<1>();
        else                       cp_wait<0>();
        __syncthreads();

        // prefetch chunk kc+3 (its stage was last read at iter kc-1; the
        // barrier above orders those reads before these writes)
        if (kc + 3 < NCHUNK) load_chunk(kc + 3);

        const uint32_t st = tiles + (kc & (NSTG - 1)) * STGB;
        #pragma unroll
        for (int ks = 0; ks < 2; ks++) {
            const uint32_t kb = ks * 32;  // 16 fp16 = 32 B
            uint32_t a[4][4], b[2][4];
            #pragma unroll
            for (int mf = 0; mf < 4; mf++)
                ldsm_x4(a[mf], st + a_off + mf * (16 * ROWB) + kb);
            #pragma unroll
            for (int nf2 = 0; nf2 < 2; nf2++)
                ldsm_x4(b[nf2], st + b_off + nf2 * (16 * ROWB) + kb);
            #pragma unroll
            for (int mf = 0; mf < 4; mf++) {
                #pragma unroll
                for (int nf = 0; nf < 4; nf++)
                    mma_fp16(acc[mf][nf], a[mf],
                             b[nf >> 1][nf & 1], b[nf >> 1][(nf & 1) + 2]);
            }
        }
    }

    // ---- epilogue: bias (+phi), fp32 stores ----
    #pragma unroll
    for (int mf = 0; mf < 4; mf++) {
        const int m0 = bm * 128 + wm * 64 + mf * 16 + (lane >> 2);
        #pragma unroll
        for (int nf = 0; nf < 4; nf++) {
            const int nc = bn * 128 + wn * 32 + nf * 8 + (lane & 3) * 2;
            const float b0 = __ldg(bias + nc), b1 = __ldg(bias + nc + 1);
            float2 lo, hi;
            lo.x = acc[mf][nf][0] + b0; lo.y = acc[mf][nf][1] + b1;
            hi.x = acc[mf][nf][2] + b0; hi.y = acc[mf][nf][3] + b1;
            if (ACT) {
                lo.x = phi_act(lo.x); lo.y = phi_act(lo.y);
                hi.x = phi_act(hi.x); hi.y = phi_act(hi.y);
            }
            *(float2*)(C + (size_t)m0 * 1024 + nc)       = lo;
            *(float2*)(C + (size_t)(m0 + 8) * 1024 + nc) = hi;
        }
    }
}

// ---------------------------------------------------------------------------
// fp32 -> two-term fp16 split [rows, 1024] -> [rows, 2048]
// MODE 0 (activation): [hi | lo]   (hi + lo == x to fp16-pair precision)
// MODE 1 (weight):     [hi | hi]
// A_cat·W_cat = (A_hi + A_lo)·W_hi ≈ A·W_hi ; dropped A·W_lo ~ 2^-12 rel
// ---------------------------------------------------------------------------
template <int MODE>
__global__ __launch_bounds__(256) void split_fp16(
    const float* __restrict__ src, __half* __restrict__ dst)
{
    const int m = blockIdx.x;
    const int c = threadIdx.x * 4;
    float4 v = *(const float4*)(src + (size_t)m * 1024 + c);
    __half h0 = __float2half(v.x), h1 = __float2half(v.y);
    __half h2 = __float2half(v.z), h3 = __float2half(v.w);
    __half2 hA(h0, h1), hB(h2, h3);
    __half* row = dst + (size_t)m * (size_t)K2;
    __half2* d0 = (__half2*)(row + c);
    __half2* d1 = (__half2*)(row + 1024 + c);
    d0[0] = hA; d0[1] = hB;
    if (MODE == 0) {  // activation: lo residual
        __half l0 = __float2half(v.x - __half2float(h0));
        __half l1 = __float2half(v.y - __half2float(h1));
        __half l2 = __float2half(v.z - __half2float(h2));
        __half l3 = __float2half(v.w - __half2float(h3));
        d1[0] = __half2(l0, l1); d1[1] = __half2(l2, l3);
    } else {          // weight: hi duplicated
        d1[0] = hA; d1[1] = hB;
    }
}

// ---------------------------------------------------------------------------
// KV summary
// ---------------------------------------------------------------------------
__global__ __launch_bounds__(256) void kv_kernel(
    const float* __restrict__ k, const float* __restrict__ v)
{
    const int bh = blockIdx.x;
    const int b  = bh >> 4;
    const int h  = bh & 15;
    const size_t base = (size_t)b * TT * DD + (size_t)h * DKK;
    const int t0 = blockIdx.y * 512;

    __shared__ float ks[16][64];
    __shared__ float vs[16][64];

    const int tid = threadIdx.x;
    const int r   = tid >> 4;
    const int c   = (tid & 15) * 4;
    const int tx  = tid & 15;
    const int ty  = tid >> 4;

    float acc[4][4];
    #pragma unroll
    for (int i = 0; i < 4; i++)
        #pragma unroll
        for (int j = 0; j < 4; j++) acc[i][j] = 0.0f;
    float ksacc = 0.0f;

    for (int tc = 0; tc < 512; tc += 16) {
        const size_t off = base + (size_t)(t0 + tc + r) * DD + c;
        *(float4*)&ks[r][c] = *(const float4*)(k + off);
        *(float4*)&vs[r][c] = *(const float4*)(v + off);
        __syncthreads();
        #pragma unroll
        for (int tt = 0; tt < 16; tt++) {
            float a[4], bb[4];
            *(float4*)a  = *(const float4*)&ks[tt][ty * 4];
            *(float4*)bb = *(const float4*)&vs[tt][tx * 4];
            #pragma unroll
            for (int i = 0; i < 4; i++)
                #pragma unroll
                for (int j = 0; j < 4; j++)
                    acc[i][j] = fmaf(a[i], bb[j], acc[i][j]);
        }
        if (tid < 64) {
            #pragma unroll
            for (int tt = 0; tt < 16; tt++) ksacc += ks[tt][tid];
        }
        __syncthreads();
    }

    float* kvb = g_kv + (size_t)bh * DKK * DKK;
    #pragma unroll
    for (int i = 0; i < 4; i++)
        #pragma unroll
        for (int j = 0; j < 4; j++)
            atomicAdd(&kvb[(ty * 4 + i) * DKK + tx * 4 + j], acc[i][j]);
    if (tid < 64) atomicAdd(&g_ksum[bh * DKK + tid], ksacc);
}

// ---------------------------------------------------------------------------
// Attention apply
// ---------------------------------------------------------------------------
__global__ __launch_bounds__(256) void attn_kernel(const float* __restrict__ q)
{
    const int bh = blockIdx.x;
    const int b  = bh >> 4;
    const int h  = bh & 15;
    const int t0 = blockIdx.y * 128;

    __shared__ float kvs[64][64];
    __shared__ float qs[128][64];
    __shared__ float zs[128];
    __shared__ float kse[64];

    const int tid = threadIdx.x;
    {
        const float4* src = (const float4*)(g_kv + (size_t)bh * DKK * DKK);
        float4* dst = (float4*)&kvs[0][0];
        #pragma unroll
        for (int i = 0; i < 4; i++) dst[i * 256 + tid] = src[i * 256 + tid];
    }
    #pragma unroll
    for (int i = 0; i < 8; i++) {
        const int f  = i * 256 + tid;
        const int tr = f >> 4;
        const int cc = (f & 15) * 4;
        *(float4*)&qs[tr][cc] =
            *(const float4*)(q + (size_t)(b * TT + t0 + tr) * DD + h * DKK + cc);
    }
    if (tid < 64) kse[tid] = g_ksum[bh * DKK + tid] + EPSV;
    __syncthreads();

    if (tid < 128) {
        float s = EPSV;
        #pragma unroll
        for (int d = 0; d < 64; d++) s = fmaf(qs[tid][d], kse[d], s);
        zs[tid] = 1.0f / s;
    }
    __syncthreads();

    const int tx = tid & 15;
    const int ty = tid >> 4;
    float acc[8][4];
    #pragma unroll
    for (int i = 0; i < 8; i++)
        #pragma unroll
        for (int j = 0; j < 4; j++) acc[i][j] = 0.0f;

    for (int d = 0; d < 64; d++) {
        float bb[4];
        *(float4*)bb = *(const float4*)&kvs[d][tx * 4];
        #pragma unroll
        for (int i = 0; i < 8; i++) {
            const float a = qs[ty * 8 + i][d];
            #pragma unroll
            for (int j = 0; j < 4; j++)
                acc[i][j] = fmaf(a, bb[j], acc[i][j]);
        }
    }

    #pragma unroll
    for (int i = 0; i < 8; i++) {
        const int t = t0 + ty * 8 + i;
        const float z = zs[ty * 8 + i];
        float4 o;
        o.x = acc[i][0] * z; o.y = acc[i][1] * z;
        o.z = acc[i][2] * z; o.w = acc[i][3] * z;
        *(float4*)(g_attn + (size_t)(b * TT + t) * DD + h * DKK + tx * 4) = o;
    }
}

// ---------------------------------------------------------------------------
extern "C" void kernel_launch(void* const* d_in, const int* in_sizes, int n_in,
                              void* d_out, int out_size)
{
    const float* x  = (const float*)d_in[0];
    const float* Wq = (const float*)d_in[1];
    const float* bq = (const float*)d_in[2];
    const float* Wk = (const float*)d_in[3];
    const float* bk = (const float*)d_in[4];
    const float* Wv = (const float*)d_in[5];
    const float* bv = (const float*)d_in[6];
    const float* Wo = (const float*)d_in[7];
    const float* bo = (const float*)d_in[8];
    float* out = (float*)d_out;

    __half *xs, *as, *wqs, *wks, *wvs, *wos;
    float *qp, *kp, *vp, *ap, *kvp, *ksp;
    cudaGetSymbolAddress((void**)&xs,  g_xs);
    cudaGetSymbolAddress((void**)&as,  g_as);
    cudaGetSymbolAddress((void**)&wqs, g_wqs);
    cudaGetSymbolAddress((void**)&wks, g_wks);
    cudaGetSymbolAddress((void**)&wvs, g_wvs);
    cudaGetSymbolAddress((void**)&wos, g_wos);
    cudaGetSymbolAddress((void**)&qp,  g_q);
    cudaGetSymbolAddress((void**)&kp,  g_k);
    cudaGetSymbolAddress((void**)&vp,  g_v);
    cudaGetSymbolAddress((void**)&ap,  g_attn);
    cudaGetSymbolAddress((void**)&kvp, g_kv);
    cudaGetSymbolAddress((void**)&ksp, g_ksum);

    cudaFuncSetAttribute(gemm_fp16<0>, cudaFuncAttributeMaxDynamicSharedMemorySize, SMEM_GEMM);
    cudaFuncSetAttribute(gemm_fp16<1>, cudaFuncAttributeMaxDynamicSharedMemorySize, SMEM_GEMM);

    // fp16 split conversions
    split_fp16<0><<<MT, 256>>>(x, xs);
    split_fp16<1><<<DD, 256>>>(Wq, wqs);
    split_fp16<1><<<DD, 256>>>(Wk, wks);
    split_fp16<1><<<DD, 256>>>(Wv, wvs);
    split_fp16<1><<<DD, 256>>>(Wo, wos);

    dim3 gg(DD / 128, MT / 128);   // (8, 128)
    gemm_fp16<1><<<gg, 256, SMEM_GEMM>>>(xs, wqs, bq, qp);
    gemm_fp16<1><<<gg, 256, SMEM_GEMM>>>(xs, wks, bk, kp);
    gemm_fp16<0><<<gg, 256, SMEM_GEMM>>>(xs, wvs, bv, vp);

    cudaMemsetAsync(kvp, 0, sizeof(float) * BB * HH * DKK * DKK);
    cudaMemsetAsync(ksp, 0, sizeof(float) * BB * HH * DKK);

    kv_kernel<<<dim3(BB * HH, 8), 256>>>(kp, vp);
    attn_kernel<<<dim3(BB * HH, TT / 128), 256>>>(qp);

    split_fp16<0><<<MT, 256>>>(ap, as);
    gemm_fp16<0><<<gg, 256, SMEM_GEMM>>>(as, wos, bo, out);
}

// round 6
// speedup vs baseline: 4.7668x; 1.6776x over previous
#include <cuda_runtime.h>
#include <cuda_fp16.h>
#include <math.h>
#include <stdint.h>

// Problem constants
static constexpr int BB  = 4;
static constexpr int TT  = 4096;
static constexpr int DD  = 1024;
static constexpr int HH  = 16;
static constexpr int DKK = 64;
static constexpr int MT  = BB * TT;      // 16384 tokens
static constexpr int KK  = DD;           // plain fp16 GEMM K = 1024
static constexpr int BKC = 32;           // K-chunk (fp16 elems)
static constexpr int NCHUNK = KK / BKC;  // 32
#define EPSV 1e-6f

// SMEM geometry: rows padded to 40 fp16 (80 B) for conflict-free ldmatrix
static constexpr int ROWB  = 80;
static constexpr int TILEB = 128 * ROWB;     // 10240 B per operand tile
static constexpr int STGB  = 2 * TILEB;      // A+B per stage
static constexpr int NSTG  = 4;
static constexpr int SMEM_GEMM = NSTG * STGB; // 81920 B

// ---------------------------------------------------------------------------
// Scratch (device globals — no allocation allowed)
// ---------------------------------------------------------------------------
__device__ __half g_xs[(size_t)MT * KK];   // x fp16     (32 MB)
__device__ __half g_as[(size_t)MT * KK];   // attn fp16  (32 MB)
__device__ __half g_wqs[DD * KK];
__device__ __half g_wks[DD * KK];
__device__ __half g_wvs[DD * KK];
__device__ __half g_wos[DD * KK];
__device__ float g_q[(size_t)MT * DD];
__device__ float g_k[(size_t)MT * DD];
__device__ float g_v[(size_t)MT * DD];
__device__ float g_attn[(size_t)MT * DD];
__device__ float g_kv[BB * HH * DKK * DKK];
__device__ float g_ksum[BB * HH * DKK];

__device__ __forceinline__ float phi_act(float x) {
    return x > 0.0f ? x + 1.0f : expf(x);
}

// ---------------------------------------------------------------------------
// PTX helpers (baseline sm_80+ features only — target is sm_103, no 'a' ISA)
// ---------------------------------------------------------------------------
__device__ __forceinline__ uint32_t smem_u32(const void* p) {
    uint32_t a;
    asm("{ .reg .u64 t; cvta.to.shared.u64 t, %1; cvt.u32.u64 %0, t; }"
        : "=r"(a) : "l"(p));
    return a;
}

#define CP_ASYNC16(sm, gp) \
    asm volatile("cp.async.cg.shared.global [%0], [%1], 16;" :: "r"(sm), "l"(gp))
#define CP_COMMIT() asm volatile("cp.async.commit_group;")
template <int N> __device__ __forceinline__ void cp_wait() {
    asm volatile("cp.async.wait_group %0;" :: "n"(N));
}

__device__ __forceinline__ void ldsm_x4(uint32_t* r, uint32_t addr) {
    asm volatile("ldmatrix.sync.aligned.m8n8.x4.shared.b16 {%0,%1,%2,%3}, [%4];"
                 : "=r"(r[0]), "=r"(r[1]), "=r"(r[2]), "=r"(r[3]) : "r"(addr));
}

__device__ __forceinline__ void mma_fp16(float* c, const uint32_t* a,
                                         uint32_t b0, uint32_t b1) {
    asm volatile(
        "mma.sync.aligned.m16n8k16.row.col.f32.f16.f16.f32 "
        "{%0,%1,%2,%3}, {%4,%5,%6,%7}, {%8,%9}, {%0,%1,%2,%3};"
        : "+f"(c[0]), "+f"(c[1]), "+f"(c[2]), "+f"(c[3])
        : "r"(a[0]), "r"(a[1]), "r"(a[2]), "r"(a[3]), "r"(b0), "r"(b1));
}

// ---------------------------------------------------------------------------
// Tensor-core GEMM (HMMA): C[M,1024] = A[M,KK]@W[1024,KK]^T + bias (+phi)
// CTA 128x128, BK=32, 8 warps (2x4), warp tile 64x32, 4-stage cp.async.
// ---------------------------------------------------------------------------
template <int ACT>
__global__ void __launch_bounds__(256, 2) gemm_fp16(
    const __half* __restrict__ A, const __half* __restrict__ W,
    const float* __restrict__ bias, float* __restrict__ C)
{
    extern __shared__ char smraw[];
    const uint32_t tiles = smem_u32(smraw);
    const int tid  = threadIdx.x;
    const int wid  = tid >> 5, lane = tid & 31;
    const int wm   = wid >> 2;            // 0..1  (M)
    const int wn   = wid & 3;             // 0..3  (N)
    const int bm   = blockIdx.y, bn = blockIdx.x;

    // ---- load geometry: each thread copies 2x16B per operand per chunk ----
    const int lrow = tid >> 1;             // 0..127
    const int lc16 = (tid & 1) * 2;        // 16B-segment pair {0,1} or {2,3}
    const uint32_t sw0 = (uint32_t)lrow * ROWB + lc16 * 16;
    const char* Ag = (const char*)(A + (size_t)(bm * 128 + lrow) * KK) + lc16 * 16;
    const char* Wg = (const char*)(W + (size_t)(bn * 128 + lrow) * KK) + lc16 * 16;

    auto load_chunk = [&](int kc) {
        const uint32_t st = tiles + (kc & (NSTG - 1)) * STGB;
        const char* ga = Ag + (size_t)kc * (BKC * 2);
        const char* gb = Wg + (size_t)kc * (BKC * 2);
        CP_ASYNC16(st + sw0,               ga);
        CP_ASYNC16(st + sw0 + 16,          ga + 16);
        CP_ASYNC16(st + TILEB + sw0,       gb);
        CP_ASYNC16(st + TILEB + sw0 + 16,  gb + 16);
        CP_COMMIT();
    };

    // ---- ldmatrix geometry ----
    const uint32_t a_off =
        (uint32_t)(wm * 64 + (lane & 15)) * ROWB + (lane >> 4) * 16;
    const uint32_t b_off =
        TILEB + (uint32_t)(wn * 32 + (lane & 15)) * ROWB + (lane >> 4) * 16;

    float acc[4][4][4];
    #pragma unroll
    for (int i = 0; i < 4; i++)
        #pragma unroll
        for (int j = 0; j < 4; j++)
            #pragma unroll
            for (int r = 0; r < 4; r++) acc[i][j][r] = 0.0f;

    load_chunk(0); load_chunk(1); load_chunk(2);

    #pragma unroll 1
    for (int kc = 0; kc < NCHUNK; kc++) {
        if (kc < NCHUNK - 2)       cp_wait<2>();
        else if (kc == NCHUNK - 2) cp_wait<1>();
        else                       cp_wait<0>();
        __syncthreads();

        // prefetch chunk kc+3 (its stage was last read at iter kc-1; the
        // barrier above orders those reads before these writes)
        if (kc + 3 < NCHUNK) load_chunk(kc + 3);

        const uint32_t st = tiles + (kc & (NSTG - 1)) * STGB;
        #pragma unroll
        for (int ks = 0; ks < 2; ks++) {
            const uint32_t kb = ks * 32;  // 16 fp16 = 32 B
            uint32_t a[4][4], b[2][4];
            #pragma unroll
            for (int mf = 0; mf < 4; mf++)
                ldsm_x4(a[mf], st + a_off + mf * (16 * ROWB) + kb);
            #pragma unroll
            for (int nf2 = 0; nf2 < 2; nf2++)
                ldsm_x4(b[nf2], st + b_off + nf2 * (16 * ROWB) + kb);
            #pragma unroll
            for (int mf = 0; mf < 4; mf++) {
                #pragma unroll
                for (int nf = 0; nf < 4; nf++)
                    mma_fp16(acc[mf][nf], a[mf],
                             b[nf >> 1][nf & 1], b[nf >> 1][(nf & 1) + 2]);
            }
        }
    }

    // ---- epilogue: bias (+phi), fp32 stores ----
    #pragma unroll
    for (int mf = 0; mf < 4; mf++) {
        const int m0 = bm * 128 + wm * 64 + mf * 16 + (lane >> 2);
        #pragma unroll
        for (int nf = 0; nf < 4; nf++) {
            const int nc = bn * 128 + wn * 32 + nf * 8 + (lane & 3) * 2;
            const float b0 = __ldg(bias + nc), b1 = __ldg(bias + nc + 1);
            float2 lo, hi;
            lo.x = acc[mf][nf][0] + b0; lo.y = acc[mf][nf][1] + b1;
            hi.x = acc[mf][nf][2] + b0; hi.y = acc[mf][nf][3] + b1;
            if (ACT) {
                lo.x = phi_act(lo.x); lo.y = phi_act(lo.y);
                hi.x = phi_act(hi.x); hi.y = phi_act(hi.y);
            }
            *(float2*)(C + (size_t)m0 * 1024 + nc)       = lo;
            *(float2*)(C + (size_t)(m0 + 8) * 1024 + nc) = hi;
        }
    }
}

// ---------------------------------------------------------------------------
// fp32 -> fp16 convert, [rows, 1024]
// ---------------------------------------------------------------------------
__global__ __launch_bounds__(256) void conv_fp16(
    const float* __restrict__ src, __half* __restrict__ dst)
{
    const int m = blockIdx.x;
    const int c = threadIdx.x * 4;
    float4 v = *(const float4*)(src + (size_t)m * 1024 + c);
    __half2* d = (__half2*)(dst + (size_t)m * (size_t)KK + c);
    d[0] = __half2(__float2half(v.x), __float2half(v.y));
    d[1] = __half2(__float2half(v.z), __float2half(v.w));
}

// ---------------------------------------------------------------------------
// KV summary: per (b,h): kv[dk,dm] += sum_t k[t,dk]*v[t,dm]
// grid (B*H, 16 t-splits of 256), 256 threads, 4x4 micro-tile, atomic reduce
// ---------------------------------------------------------------------------
__global__ __launch_bounds__(256) void kv_kernel(
    const float* __restrict__ k, const float* __restrict__ v)
{
    const int bh = blockIdx.x;
    const int b  = bh >> 4;
    const int h  = bh & 15;
    const size_t base = (size_t)b * TT * DD + (size_t)h * DKK;
    const int t0 = blockIdx.y * 256;

    __shared__ float ks[16][64];
    __shared__ float vs[16][64];

    const int tid = threadIdx.x;
    const int r   = tid >> 4;
    const int c   = (tid & 15) * 4;
    const int tx  = tid & 15;
    const int ty  = tid >> 4;

    float acc[4][4];
    #pragma unroll
    for (int i = 0; i < 4; i++)
        #pragma unroll
        for (int j = 0; j < 4; j++) acc[i][j] = 0.0f;
    float ksacc = 0.0f;

    for (int tc = 0; tc < 256; tc += 16) {
        const size_t off = base + (size_t)(t0 + tc + r) * DD + c;
        *(float4*)&ks[r][c] = *(const float4*)(k + off);
        *(float4*)&vs[r][c] = *(const float4*)(v + off);
        __syncthreads();
        #pragma unroll
        for (int tt = 0; tt < 16; tt++) {
            float a[4], bb[4];
            *(float4*)a  = *(const float4*)&ks[tt][ty * 4];
            *(float4*)bb = *(const float4*)&vs[tt][tx * 4];
            #pragma unroll
            for (int i = 0; i < 4; i++)
                #pragma unroll
                for (int j = 0; j < 4; j++)
                    acc[i][j] = fmaf(a[i], bb[j], acc[i][j]);
        }
        if (tid < 64) {
            #pragma unroll
            for (int tt = 0; tt < 16; tt++) ksacc += ks[tt][tid];
        }
        __syncthreads();
    }

    float* kvb = g_kv + (size_t)bh * DKK * DKK;
    #pragma unroll
    for (int i = 0; i < 4; i++)
        #pragma unroll
        for (int j = 0; j < 4; j++)
            atomicAdd(&kvb[(ty * 4 + i) * DKK + tx * 4 + j], acc[i][j]);
    if (tid < 64) atomicAdd(&g_ksum[bh * DKK + tid], ksacc);
}

// ---------------------------------------------------------------------------
// Attention apply: out[t,dm] = z[t] * sum_dk q[t,dk]*kv[dk,dm]
// ---------------------------------------------------------------------------
__global__ __launch_bounds__(256) void attn_kernel(const float* __restrict__ q)
{
    const int bh = blockIdx.x;
    const int b  = bh >> 4;
    const int h  = bh & 15;
    const int t0 = blockIdx.y * 128;

    __shared__ float kvs[64][64];
    __shared__ float qs[128][64];
    __shared__ float zs[128];
    __shared__ float kse[64];

    const int tid = threadIdx.x;
    {
        const float4* src = (const float4*)(g_kv + (size_t)bh * DKK * DKK);
        float4* dst = (float4*)&kvs[0][0];
        #pragma unroll
        for (int i = 0; i < 4; i++) dst[i * 256 + tid] = src[i * 256 + tid];
    }
    #pragma unroll
    for (int i = 0; i < 8; i++) {
        const int f  = i * 256 + tid;
        const int tr = f >> 4;
        const int cc = (f & 15) * 4;
        *(float4*)&qs[tr][cc] =
            *(const float4*)(q + (size_t)(b * TT + t0 + tr) * DD + h * DKK + cc);
    }
    if (tid < 64) kse[tid] = g_ksum[bh * DKK + tid] + EPSV;
    __syncthreads();

    if (tid < 128) {
        float s = EPSV;
        #pragma unroll
        for (int d = 0; d < 64; d++) s = fmaf(qs[tid][d], kse[d], s);
        zs[tid] = 1.0f / s;
    }
    __syncthreads();

    const int tx = tid & 15;
    const int ty = tid >> 4;
    float acc[8][4];
    #pragma unroll
    for (int i = 0; i < 8; i++)
        #pragma unroll
        for (int j = 0; j < 4; j++) acc[i][j] = 0.0f;

    for (int d = 0; d < 64; d++) {
        float bb[4];
        *(float4*)bb = *(const float4*)&kvs[d][tx * 4];
        #pragma unroll
        for (int i = 0; i < 8; i++) {
            const float a = qs[ty * 8 + i][d];
            #pragma unroll
            for (int j = 0; j < 4; j++)
                acc[i][j] = fmaf(a, bb[j], acc[i][j]);
        }
    }

    #pragma unroll
    for (int i = 0; i < 8; i++) {
        const int t = t0 + ty * 8 + i;
        const float z = zs[ty * 8 + i];
        float4 o;
        o.x = acc[i][0] * z; o.y = acc[i][1] * z;
        o.z = acc[i][2] * z; o.w = acc[i][3] * z;
        *(float4*)(g_attn + (size_t)(b * TT + t) * DD + h * DKK + tx * 4) = o;
    }
}

// ---------------------------------------------------------------------------
extern "C" void kernel_launch(void* const* d_in, const int* in_sizes, int n_in,
                              void* d_out, int out_size)
{
    const float* x  = (const float*)d_in[0];
    const float* Wq = (const float*)d_in[1];
    const float* bq = (const float*)d_in[2];
    const float* Wk = (const float*)d_in[3];
    const float* bk = (const float*)d_in[4];
    const float* Wv = (const float*)d_in[5];
    const float* bv = (const float*)d_in[6];
    const float* Wo = (const float*)d_in[7];
    const float* bo = (const float*)d_in[8];
    float* out = (float*)d_out;

    __half *xs, *as, *wqs, *wks, *wvs, *wos;
    float *qp, *kp, *vp, *ap, *kvp, *ksp;
    cudaGetSymbolAddress((void**)&xs,  g_xs);
    cudaGetSymbolAddress((void**)&as,  g_as);
    cudaGetSymbolAddress((void**)&wqs, g_wqs);
    cudaGetSymbolAddress((void**)&wks, g_wks);
    cudaGetSymbolAddress((void**)&wvs, g_wvs);
    cudaGetSymbolAddress((void**)&wos, g_wos);
    cudaGetSymbolAddress((void**)&qp,  g_q);
    cudaGetSymbolAddress((void**)&kp,  g_k);
    cudaGetSymbolAddress((void**)&vp,  g_v);
    cudaGetSymbolAddress((void**)&ap,  g_attn);
    cudaGetSymbolAddress((void**)&kvp, g_kv);
    cudaGetSymbolAddress((void**)&ksp, g_ksum);

    cudaFuncSetAttribute(gemm_fp16<0>, cudaFuncAttributeMaxDynamicSharedMemorySize, SMEM_GEMM);
    cudaFuncSetAttribute(gemm_fp16<1>, cudaFuncAttributeMaxDynamicSharedMemorySize, SMEM_GEMM);

    // fp16 conversions
    conv_fp16<<<MT, 256>>>(x, xs);
    conv_fp16<<<DD, 256>>>(Wq, wqs);
    conv_fp16<<<DD, 256>>>(Wk, wks);
    conv_fp16<<<DD, 256>>>(Wv, wvs);
    conv_fp16<<<DD, 256>>>(Wo, wos);

    dim3 gg(DD / 128, MT / 128);   // (8, 128)
    gemm_fp16<1><<<gg, 256, SMEM_GEMM>>>(xs, wqs, bq, qp);
    gemm_fp16<1><<<gg, 256, SMEM_GEMM>>>(xs, wks, bk, kp);
    gemm_fp16<0><<<gg, 256, SMEM_GEMM>>>(xs, wvs, bv, vp);

    cudaMemsetAsync(kvp, 0, sizeof(float) * BB * HH * DKK * DKK);
    cudaMemsetAsync(ksp, 0, sizeof(float) * BB * HH * DKK);

    kv_kernel<<<dim3(BB * HH, 16), 256>>>(kp, vp);
    attn_kernel<<<dim3(BB * HH, TT / 128), 256>>>(qp);

    conv_fp16<<<MT, 256>>>(ap, as);
    gemm_fp16<0><<<gg, 256, SMEM_GEMM>>>(as, wos, bo, out);
}

// round 7
// speedup vs baseline: 4.9372x; 1.0358x over previous
#include <cuda_runtime.h>
#include <cuda_fp16.h>
#include <math.h>
#include <stdint.h>

// Problem constants
static constexpr int BB  = 4;
static constexpr int TT  = 4096;
static constexpr int DD  = 1024;
static constexpr int HH  = 16;
static constexpr int DKK = 64;
static constexpr int MT  = BB * TT;      // 16384 tokens
static constexpr int KK  = DD;           // fp16 GEMM K = 1024
static constexpr int BKC = 32;           // K-chunk (fp16 elems)
static constexpr int NCHUNK = KK / BKC;  // 32
#define EPSV 1e-6f

// SMEM geometry: rows padded to 40 fp16 (80 B) for conflict-free ldmatrix
static constexpr int ROWB  = 80;
static constexpr int TILEB = 128 * ROWB;     // 10240 B per operand tile
static constexpr int STGB  = 2 * TILEB;      // A+B per stage
static constexpr int NSTG  = 4;
static constexpr int SMEM_GEMM = NSTG * STGB; // 81920 B

// ---------------------------------------------------------------------------
// Scratch (device globals — no allocation allowed)
// ---------------------------------------------------------------------------
__device__ __half g_xs[(size_t)MT * KK];      // x fp16           (32 MB)
__device__ __half g_as[(size_t)MT * KK];      // attn fp16        (32 MB)
__device__ __half g_wqkv[3 * DD * KK];        // packed Wq|Wk|Wv fp16
__device__ __half g_wos[DD * KK];             // Wo fp16
__device__ float g_q[(size_t)MT * DD];
__device__ float g_k[(size_t)MT * DD];
__device__ float g_v[(size_t)MT * DD];
__device__ float g_kv[BB * HH * DKK * DKK];
__device__ float g_ksum[BB * HH * DKK];

__device__ __forceinline__ float phi_act(float x) {
    return x > 0.0f ? x + 1.0f : expf(x);
}

// ---------------------------------------------------------------------------
// PTX helpers (baseline sm_80+ features only — target is sm_103, no 'a' ISA)
// ---------------------------------------------------------------------------
__device__ __forceinline__ uint32_t smem_u32(const void* p) {
    uint32_t a;
    asm("{ .reg .u64 t; cvta.to.shared.u64 t, %1; cvt.u32.u64 %0, t; }"
        : "=r"(a) : "l"(p));
    return a;
}

#define CP_ASYNC16(sm, gp) \
    asm volatile("cp.async.cg.shared.global [%0], [%1], 16;" :: "r"(sm), "l"(gp))
#define CP_COMMIT() asm volatile("cp.async.commit_group;")
template <int N> __device__ __forceinline__ void cp_wait() {
    asm volatile("cp.async.wait_group %0;" :: "n"(N));
}

__device__ __forceinline__ void ldsm_x4(uint32_t* r, uint32_t addr) {
    asm volatile("ldmatrix.sync.aligned.m8n8.x4.shared.b16 {%0,%1,%2,%3}, [%4];"
                 : "=r"(r[0]), "=r"(r[1]), "=r"(r[2]), "=r"(r[3]) : "r"(addr));
}

__device__ __forceinline__ void mma_fp16(float* c, const uint32_t* a,
                                         uint32_t b0, uint32_t b1) {
    asm volatile(
        "mma.sync.aligned.m16n8k16.row.col.f32.f16.f16.f32 "
        "{%0,%1,%2,%3}, {%4,%5,%6,%7}, {%8,%9}, {%0,%1,%2,%3};"
        : "+f"(c[0]), "+f"(c[1]), "+f"(c[2]), "+f"(c[3])
        : "r"(a[0]), "r"(a[1]), "r"(a[2]), "r"(a[3]), "r"(b0), "r"(b1));
}

// ---------------------------------------------------------------------------
// GEMM mainloop core (shared by both gemm kernels).
// Produces acc[4][4][4] for this thread's 64x32 warp tile slice.
// ---------------------------------------------------------------------------
struct GemmCore {
    uint32_t tiles, sw0, a_off, b_off;
    const char *Ag, *Wg;
    float acc[4][4][4];

    __device__ __forceinline__ void init(uint32_t tiles_, int tid,
                                         const __half* A, const __half* W,
                                         int bm, int bn) {
        tiles = tiles_;
        const int wid  = tid >> 5, lane = tid & 31;
        const int wm   = wid >> 2, wn = wid & 3;
        const int lrow = tid >> 1;
        const int lc16 = (tid & 1) * 2;
        sw0 = (uint32_t)lrow * ROWB + lc16 * 16;
        Ag = (const char*)(A + (size_t)(bm * 128 + lrow) * KK) + lc16 * 16;
        Wg = (const char*)(W + (size_t)(bn * 128 + lrow) * KK) + lc16 * 16;
        a_off = (uint32_t)(wm * 64 + (lane & 15)) * ROWB + (lane >> 4) * 16;
        b_off = TILEB + (uint32_t)(wn * 32 + (lane & 15)) * ROWB + (lane >> 4) * 16;
        #pragma unroll
        for (int i = 0; i < 4; i++)
            #pragma unroll
            for (int j = 0; j < 4; j++)
                #pragma unroll
                for (int r = 0; r < 4; r++) acc[i][j][r] = 0.0f;
    }

    __device__ __forceinline__ void load_chunk(int kc) {
        const uint32_t st = tiles + (kc & (NSTG - 1)) * STGB;
        const char* ga = Ag + (size_t)kc * (BKC * 2);
        const char* gb = Wg + (size_t)kc * (BKC * 2);
        CP_ASYNC16(st + sw0,              ga);
        CP_ASYNC16(st + sw0 + 16,         ga + 16);
        CP_ASYNC16(st + TILEB + sw0,      gb);
        CP_ASYNC16(st + TILEB + sw0 + 16, gb + 16);
        CP_COMMIT();
    }

    __device__ __forceinline__ void run() {
        load_chunk(0); load_chunk(1); load_chunk(2);
        #pragma unroll 1
        for (int kc = 0; kc < NCHUNK; kc++) {
            if (kc < NCHUNK - 2)       cp_wait<2>();
            else if (kc == NCHUNK - 2) cp_wait<1>();
            else                       cp_wait<0>();
            __syncthreads();
            if (kc + 3 < NCHUNK) load_chunk(kc + 3);

            const uint32_t st = tiles + (kc & (NSTG - 1)) * STGB;
            #pragma unroll
            for (int ks = 0; ks < 2; ks++) {
                const uint32_t kb = ks * 32;
                uint32_t a[4][4], b[2][4];
                #pragma unroll
                for (int mf = 0; mf < 4; mf++)
                    ldsm_x4(a[mf], st + a_off + mf * (16 * ROWB) + kb);
                #pragma unroll
                for (int nf2 = 0; nf2 < 2; nf2++)
                    ldsm_x4(b[nf2], st + b_off + nf2 * (16 * ROWB) + kb);
                #pragma unroll
                for (int mf = 0; mf < 4; mf++) {
                    #pragma unroll
                    for (int nf = 0; nf < 4; nf++)
                        mma_fp16(acc[mf][nf], a[mf],
                                 b[nf >> 1][nf & 1], b[nf >> 1][(nf & 1) + 2]);
                }
            }
        }
    }
};

// ---------------------------------------------------------------------------
// Fused QKV GEMM: N=3072 (seg 0=Q+phi, 1=K+phi, 2=V) -> fp32 outputs
// grid (24, 128)
// ---------------------------------------------------------------------------
__global__ void __launch_bounds__(256, 2) gemm_qkv(
    const __half* __restrict__ A, const __half* __restrict__ Wqkv,
    const float* __restrict__ bq, const float* __restrict__ bk,
    const float* __restrict__ bv,
    float* __restrict__ Cq, float* __restrict__ Ck, float* __restrict__ Cv)
{
    extern __shared__ char smraw[];
    const int tid = threadIdx.x;
    const int wid = tid >> 5, lane = tid & 31;
    const int wm  = wid >> 2, wn = wid & 3;
    const int bm  = blockIdx.y, bn = blockIdx.x;

    const int seg = bn >> 3;                 // 0=q, 1=k, 2=v
    const float* bias = seg == 0 ? bq : (seg == 1 ? bk : bv);
    float* C = seg == 0 ? Cq : (seg == 1 ? Ck : Cv);
    const bool act = seg < 2;

    GemmCore g;
    g.init(smem_u32(smraw), tid, A, Wqkv, bm, bn);
    g.run();

    #pragma unroll
    for (int mf = 0; mf < 4; mf++) {
        const int m0 = bm * 128 + wm * 64 + mf * 16 + (lane >> 2);
        #pragma unroll
        for (int nf = 0; nf < 4; nf++) {
            const int nc = (bn & 7) * 128 + wn * 32 + nf * 8 + (lane & 3) * 2;
            const float b0 = __ldg(bias + nc), b1 = __ldg(bias + nc + 1);
            float2 lo, hi;
            lo.x = g.acc[mf][nf][0] + b0; lo.y = g.acc[mf][nf][1] + b1;
            hi.x = g.acc[mf][nf][2] + b0; hi.y = g.acc[mf][nf][3] + b1;
            if (act) {
                lo.x = phi_act(lo.x); lo.y = phi_act(lo.y);
                hi.x = phi_act(hi.x); hi.y = phi_act(hi.y);
            }
            *(float2*)(C + (size_t)m0 * 1024 + nc)       = lo;
            *(float2*)(C + (size_t)(m0 + 8) * 1024 + nc) = hi;
        }
    }
}

// ---------------------------------------------------------------------------
// Output GEMM: out = attn_fp16 @ Wo^T + bo  -> fp32
// ---------------------------------------------------------------------------
__global__ void __launch_bounds__(256, 2) gemm_out(
    const __half* __restrict__ A, const __half* __restrict__ W,
    const float* __restrict__ bias, float* __restrict__ C)
{
    extern __shared__ char smraw[];
    const int tid = threadIdx.x;
    const int wid = tid >> 5, lane = tid & 31;
    const int wm  = wid >> 2, wn = wid & 3;
    const int bm  = blockIdx.y, bn = blockIdx.x;

    GemmCore g;
    g.init(smem_u32(smraw), tid, A, W, bm, bn);
    g.run();

    #pragma unroll
    for (int mf = 0; mf < 4; mf++) {
        const int m0 = bm * 128 + wm * 64 + mf * 16 + (lane >> 2);
        #pragma unroll
        for (int nf = 0; nf < 4; nf++) {
            const int nc = bn * 128 + wn * 32 + nf * 8 + (lane & 3) * 2;
            const float b0 = __ldg(bias + nc), b1 = __ldg(bias + nc + 1);
            float2 lo, hi;
            lo.x = g.acc[mf][nf][0] + b0; lo.y = g.acc[mf][nf][1] + b1;
            hi.x = g.acc[mf][nf][2] + b0; hi.y = g.acc[mf][nf][3] + b1;
            *(float2*)(C + (size_t)m0 * 1024 + nc)       = lo;
            *(float2*)(C + (size_t)(m0 + 8) * 1024 + nc) = hi;
        }
    }
}

// ---------------------------------------------------------------------------
// fp32 -> fp16 convert, [rows, 1024]
// ---------------------------------------------------------------------------
__global__ __launch_bounds__(256) void conv_fp16(
    const float* __restrict__ src, __half* __restrict__ dst)
{
    const int m = blockIdx.x;
    const int c = threadIdx.x * 4;
    float4 v = *(const float4*)(src + (size_t)m * 1024 + c);
    __half2* d = (__half2*)(dst + (size_t)m * 1024 + c);
    d[0] = __half2(__float2half(v.x), __float2half(v.y));
    d[1] = __half2(__float2half(v.z), __float2half(v.w));
}

// ---------------------------------------------------------------------------
// KV summary: per (b,h): kv[dk,dm] += sum_t k[t,dk]*v[t,dm]
// grid (B*H, 16 t-splits of 256), 256 threads, 4x4 micro-tile, atomic reduce
// ---------------------------------------------------------------------------
__global__ __launch_bounds__(256) void kv_kernel(
    const float* __restrict__ k, const float* __restrict__ v)
{
    const int bh = blockIdx.x;
    const int b  = bh >> 4;
    const int h  = bh & 15;
    const size_t base = (size_t)b * TT * DD + (size_t)h * DKK;
    const int t0 = blockIdx.y * 256;

    __shared__ float ks[16][64];
    __shared__ float vs[16][64];

    const int tid = threadIdx.x;
    const int r   = tid >> 4;
    const int c   = (tid & 15) * 4;
    const int tx  = tid & 15;
    const int ty  = tid >> 4;

    float acc[4][4];
    #pragma unroll
    for (int i = 0; i < 4; i++)
        #pragma unroll
        for (int j = 0; j < 4; j++) acc[i][j] = 0.0f;
    float ksacc = 0.0f;

    for (int tc = 0; tc < 256; tc += 16) {
        const size_t off = base + (size_t)(t0 + tc + r) * DD + c;
        *(float4*)&ks[r][c] = *(const float4*)(k + off);
        *(float4*)&vs[r][c] = *(const float4*)(v + off);
        __syncthreads();
        #pragma unroll
        for (int tt = 0; tt < 16; tt++) {
            float a[4], bb[4];
            *(float4*)a  = *(const float4*)&ks[tt][ty * 4];
            *(float4*)bb = *(const float4*)&vs[tt][tx * 4];
            #pragma unroll
            for (int i = 0; i < 4; i++)
                #pragma unroll
                for (int j = 0; j < 4; j++)
                    acc[i][j] = fmaf(a[i], bb[j], acc[i][j]);
        }
        if (tid < 64) {
            #pragma unroll
            for (int tt = 0; tt < 16; tt++) ksacc += ks[tt][tid];
        }
        __syncthreads();
    }

    float* kvb = g_kv + (size_t)bh * DKK * DKK;
    #pragma unroll
    for (int i = 0; i < 4; i++)
        #pragma unroll
        for (int j = 0; j < 4; j++)
            atomicAdd(&kvb[(ty * 4 + i) * DKK + tx * 4 + j], acc[i][j]);
    if (tid < 64) atomicAdd(&g_ksum[bh * DKK + tid], ksacc);
}

// ---------------------------------------------------------------------------
// Attention apply: out[t,dm] = z[t] * sum_dk q[t,dk]*kv[dk,dm]  -> fp16
// ---------------------------------------------------------------------------
__global__ __launch_bounds__(256) void attn_kernel(
    const float* __restrict__ q, __half* __restrict__ out)
{
    const int bh = blockIdx.x;
    const int b  = bh >> 4;
    const int h  = bh & 15;
    const int t0 = blockIdx.y * 128;

    __shared__ float kvs[64][64];
    __shared__ float qs[128][64];
    __shared__ float zs[128];
    __shared__ float kse[64];

    const int tid = threadIdx.x;
    {
        const float4* src = (const float4*)(g_kv + (size_t)bh * DKK * DKK);
        float4* dst = (float4*)&kvs[0][0];
        #pragma unroll
        for (int i = 0; i < 4; i++) dst[i * 256 + tid] = src[i * 256 + tid];
    }
    #pragma unroll
    for (int i = 0; i < 8; i++) {
        const int f  = i * 256 + tid;
        const int tr = f >> 4;
        const int cc = (f & 15) * 4;
        *(float4*)&qs[tr][cc] =
            *(const float4*)(q + (size_t)(b * TT + t0 + tr) * DD + h * DKK + cc);
    }
    if (tid < 64) kse[tid] = g_ksum[bh * DKK + tid] + EPSV;
    __syncthreads();

    if (tid < 128) {
        float s = EPSV;
        #pragma unroll
        for (int d = 0; d < 64; d++) s = fmaf(qs[tid][d], kse[d], s);
        zs[tid] = 1.0f / s;
    }
    __syncthreads();

    const int tx = tid & 15;
    const int ty = tid >> 4;
    float acc[8][4];
    #pragma unroll
    for (int i = 0; i < 8; i++)
        #pragma unroll
        for (int j = 0; j < 4; j++) acc[i][j] = 0.0f;

    for (int d = 0; d < 64; d++) {
        float bb[4];
        *(float4*)bb = *(const float4*)&kvs[d][tx * 4];
        #pragma unroll
        for (int i = 0; i < 8; i++) {
            const float a = qs[ty * 8 + i][d];
            #pragma unroll
            for (int j = 0; j < 4; j++)
                acc[i][j] = fmaf(a, bb[j], acc[i][j]);
        }
    }

    #pragma unroll
    for (int i = 0; i < 8; i++) {
        const int t = t0 + ty * 8 + i;
        const float z = zs[ty * 8 + i];
        __half2* o = (__half2*)(out + (size_t)(b * TT + t) * 1024 + h * DKK + tx * 4);
        o[0] = __half2(__float2half(acc[i][0] * z), __float2half(acc[i][1] * z));
        o[1] = __half2(__float2half(acc[i][2] * z), __float2half(acc[i][3] * z));
    }
}

// ---------------------------------------------------------------------------
extern "C" void kernel_launch(void* const* d_in, const int* in_sizes, int n_in,
                              void* d_out, int out_size)
{
    const float* x  = (const float*)d_in[0];
    const float* Wq = (const float*)d_in[1];
    const float* bq = (const float*)d_in[2];
    const float* Wk = (const float*)d_in[3];
    const float* bk = (const float*)d_in[4];
    const float* Wv = (const float*)d_in[5];
    const float* bv = (const float*)d_in[6];
    const float* Wo = (const float*)d_in[7];
    const float* bo = (const float*)d_in[8];
    float* out = (float*)d_out;

    __half *xs, *as, *wqkv, *wos;
    float *qp, *kp, *vp, *kvp, *ksp;
    cudaGetSymbolAddress((void**)&xs,   g_xs);
    cudaGetSymbolAddress((void**)&as,   g_as);
    cudaGetSymbolAddress((void**)&wqkv, g_wqkv);
    cudaGetSymbolAddress((void**)&wos,  g_wos);
    cudaGetSymbolAddress((void**)&qp,   g_q);
    cudaGetSymbolAddress((void**)&kp,   g_k);
    cudaGetSymbolAddress((void**)&vp,   g_v);
    cudaGetSymbolAddress((void**)&kvp,  g_kv);
    cudaGetSymbolAddress((void**)&ksp,  g_ksum);

    cudaFuncSetAttribute(gemm_qkv, cudaFuncAttributeMaxDynamicSharedMemorySize, SMEM_GEMM);
    cudaFuncSetAttribute(gemm_out, cudaFuncAttributeMaxDynamicSharedMemorySize, SMEM_GEMM);

    // memsets first (off the critical GEMM path)
    cudaMemsetAsync(kvp, 0, sizeof(float) * BB * HH * DKK * DKK);
    cudaMemsetAsync(ksp, 0, sizeof(float) * BB * HH * DKK);

    // fp16 conversions (weights packed into one QKV buffer)
    conv_fp16<<<MT, 256>>>(x, xs);
    conv_fp16<<<DD, 256>>>(Wq, wqkv);
    conv_fp16<<<DD, 256>>>(Wk, wqkv + (size_t)DD * KK);
    conv_fp16<<<DD, 256>>>(Wv, wqkv + (size_t)2 * DD * KK);
    conv_fp16<<<DD, 256>>>(Wo, wos);

    // fused QKV GEMM: grid (24, 128)
    gemm_qkv<<<dim3(24, MT / 128), 256, SMEM_GEMM>>>(
        xs, wqkv, bq, bk, bv, qp, kp, vp);

    kv_kernel<<<dim3(BB * HH, 16), 256>>>(kp, vp);
    attn_kernel<<<dim3(BB * HH, TT / 128), 256>>>(qp, as);

    gemm_out<<<dim3(DD / 128, MT / 128), 256, SMEM_GEMM>>>(as, wos, bo, out);
}

// round 8
// speedup vs baseline: 5.7539x; 1.1654x over previous
#include <cuda_runtime.h>
#include <cuda_fp16.h>
#include <math.h>
#include <stdint.h>

// Problem constants
static constexpr int BB  = 4;
static constexpr int TT  = 4096;
static constexpr int DD  = 1024;
static constexpr int HH  = 16;
static constexpr int DKK = 64;
static constexpr int MT  = BB * TT;      // 16384 tokens
static constexpr int KK  = DD;           // fp16 GEMM K = 1024
static constexpr int BKC = 32;           // K-chunk (fp16 elems)
static constexpr int NCHUNK = KK / BKC;  // 32
#define EPSV 1e-6f

// GEMM SMEM geometry: rows padded to 40 fp16 (80 B) for conflict-free ldmatrix
static constexpr int ROWB  = 80;
static constexpr int TILEB = 128 * ROWB;
static constexpr int STGB  = 2 * TILEB;
static constexpr int NSTG  = 4;
static constexpr int SMEM_GEMM = NSTG * STGB; // 81920 B

// kv/attn smem row stride for 64-wide fp16 tiles: 128B data + 16B pad
static constexpr int RS64 = 144;

// ---------------------------------------------------------------------------
// Scratch (device globals — no allocation allowed)
// ---------------------------------------------------------------------------
__device__ __half g_xs[(size_t)MT * KK];      // x fp16
__device__ __half g_as[(size_t)MT * KK];      // attn out fp16
__device__ __half g_wqkv[3 * DD * KK];        // packed Wq|Wk|Wv fp16
__device__ __half g_wos[DD * KK];             // Wo fp16
__device__ __half g_q16[(size_t)MT * DD];
__device__ __half g_k16[(size_t)MT * DD];
__device__ __half g_v16[(size_t)MT * DD];
__device__ float  g_kv[BB * HH * DKK * DKK];
__device__ __half g_kvT[BB * HH * DKK * DKK]; // transposed fp16 kv
__device__ float  g_ksum[BB * HH * DKK];
__device__ float  g_kse[BB * HH * DKK];       // ksum + eps

__device__ __forceinline__ float phi_act(float x) {
    return x > 0.0f ? x + 1.0f : expf(x);
}

// ---------------------------------------------------------------------------
// PTX helpers (baseline sm_80+ features only)
// ---------------------------------------------------------------------------
__device__ __forceinline__ uint32_t smem_u32(const void* p) {
    uint32_t a;
    asm("{ .reg .u64 t; cvta.to.shared.u64 t, %1; cvt.u32.u64 %0, t; }"
        : "=r"(a) : "l"(p));
    return a;
}

#define CP_ASYNC16(sm, gp) \
    asm volatile("cp.async.cg.shared.global [%0], [%1], 16;" :: "r"(sm), "l"(gp))
#define CP_COMMIT() asm volatile("cp.async.commit_group;")
template <int N> __device__ __forceinline__ void cp_wait() {
    asm volatile("cp.async.wait_group %0;" :: "n"(N));
}

__device__ __forceinline__ void ldsm_x4(uint32_t* r, uint32_t addr) {
    asm volatile("ldmatrix.sync.aligned.m8n8.x4.shared.b16 {%0,%1,%2,%3}, [%4];"
                 : "=r"(r[0]), "=r"(r[1]), "=r"(r[2]), "=r"(r[3]) : "r"(addr));
}
__device__ __forceinline__ void ldsm_x4_t(uint32_t* r, uint32_t addr) {
    asm volatile("ldmatrix.sync.aligned.m8n8.x4.trans.shared.b16 {%0,%1,%2,%3}, [%4];"
                 : "=r"(r[0]), "=r"(r[1]), "=r"(r[2]), "=r"(r[3]) : "r"(addr));
}

__device__ __forceinline__ void mma_fp16(float* c, const uint32_t* a,
                                         uint32_t b0, uint32_t b1) {
    asm volatile(
        "mma.sync.aligned.m16n8k16.row.col.f32.f16.f16.f32 "
        "{%0,%1,%2,%3}, {%4,%5,%6,%7}, {%8,%9}, {%0,%1,%2,%3};"
        : "+f"(c[0]), "+f"(c[1]), "+f"(c[2]), "+f"(c[3])
        : "r"(a[0]), "r"(a[1]), "r"(a[2]), "r"(a[3]), "r"(b0), "r"(b1));
}

// ---------------------------------------------------------------------------
// GEMM mainloop core (as in R7 — at the HMMA issue floor)
// ---------------------------------------------------------------------------
struct GemmCore {
    uint32_t tiles, sw0, a_off, b_off;
    const char *Ag, *Wg;
    float acc[4][4][4];

    __device__ __forceinline__ void init(uint32_t tiles_, int tid,
                                         const __half* A, const __half* W,
                                         int bm, int bn) {
        tiles = tiles_;
        const int wid  = tid >> 5, lane = tid & 31;
        const int wm   = wid >> 2, wn = wid & 3;
        const int lrow = tid >> 1;
        const int lc16 = (tid & 1) * 2;
        sw0 = (uint32_t)lrow * ROWB + lc16 * 16;
        Ag = (const char*)(A + (size_t)(bm * 128 + lrow) * KK) + lc16 * 16;
        Wg = (const char*)(W + (size_t)(bn * 128 + lrow) * KK) + lc16 * 16;
        a_off = (uint32_t)(wm * 64 + (lane & 15)) * ROWB + (lane >> 4) * 16;
        b_off = TILEB + (uint32_t)(wn * 32 + (lane & 15)) * ROWB + (lane >> 4) * 16;
        #pragma unroll
        for (int i = 0; i < 4; i++)
            #pragma unroll
            for (int j = 0; j < 4; j++)
                #pragma unroll
                for (int r = 0; r < 4; r++) acc[i][j][r] = 0.0f;
    }

    __device__ __forceinline__ void load_chunk(int kc) {
        const uint32_t st = tiles + (kc & (NSTG - 1)) * STGB;
        const char* ga = Ag + (size_t)kc * (BKC * 2);
        const char* gb = Wg + (size_t)kc * (BKC * 2);
        CP_ASYNC16(st + sw0,              ga);
        CP_ASYNC16(st + sw0 + 16,         ga + 16);
        CP_ASYNC16(st + TILEB + sw0,      gb);
        CP_ASYNC16(st + TILEB + sw0 + 16, gb + 16);
        CP_COMMIT();
    }

    __device__ __forceinline__ void run() {
        load_chunk(0); load_chunk(1); load_chunk(2);
        #pragma unroll 1
        for (int kc = 0; kc < NCHUNK; kc++) {
            if (kc < NCHUNK - 2)       cp_wait<2>();
            else if (kc == NCHUNK - 2) cp_wait<1>();
            else                       cp_wait<0>();
            __syncthreads();
            if (kc + 3 < NCHUNK) load_chunk(kc + 3);

            const uint32_t st = tiles + (kc & (NSTG - 1)) * STGB;
            #pragma unroll
            for (int ks = 0; ks < 2; ks++) {
                const uint32_t kb = ks * 32;
                uint32_t a[4][4], b[2][4];
                #pragma unroll
                for (int mf = 0; mf < 4; mf++)
                    ldsm_x4(a[mf], st + a_off + mf * (16 * ROWB) + kb);
                #pragma unroll
                for (int nf2 = 0; nf2 < 2; nf2++)
                    ldsm_x4(b[nf2], st + b_off + nf2 * (16 * ROWB) + kb);
                #pragma unroll
                for (int mf = 0; mf < 4; mf++) {
                    #pragma unroll
                    for (int nf = 0; nf < 4; nf++)
                        mma_fp16(acc[mf][nf], a[mf],
                                 b[nf >> 1][nf & 1], b[nf >> 1][(nf & 1) + 2]);
                }
            }
        }
    }
};

// ---------------------------------------------------------------------------
// Fused QKV GEMM -> fp16 outputs (seg 0=Q+phi, 1=K+phi, 2=V); grid (24, 128)
// ---------------------------------------------------------------------------
__global__ void __launch_bounds__(256, 2) gemm_qkv(
    const __half* __restrict__ A, const __half* __restrict__ Wqkv,
    const float* __restrict__ bq, const float* __restrict__ bk,
    const float* __restrict__ bv,
    __half* __restrict__ Cq, __half* __restrict__ Ck, __half* __restrict__ Cv)
{
    extern __shared__ char smraw[];
    const int tid = threadIdx.x;
    const int wid = tid >> 5, lane = tid & 31;
    const int wm  = wid >> 2, wn = wid & 3;
    const int bm  = blockIdx.y, bn = blockIdx.x;

    const int seg = bn >> 3;
    const float* bias = seg == 0 ? bq : (seg == 1 ? bk : bv);
    __half* C = seg == 0 ? Cq : (seg == 1 ? Ck : Cv);
    const bool act = seg < 2;

    GemmCore g;
    g.init(smem_u32(smraw), tid, A, Wqkv, bm, bn);
    g.run();

    #pragma unroll
    for (int mf = 0; mf < 4; mf++) {
        const int m0 = bm * 128 + wm * 64 + mf * 16 + (lane >> 2);
        #pragma unroll
        for (int nf = 0; nf < 4; nf++) {
            const int nc = (bn & 7) * 128 + wn * 32 + nf * 8 + (lane & 3) * 2;
            const float b0 = __ldg(bias + nc), b1 = __ldg(bias + nc + 1);
            float l0 = g.acc[mf][nf][0] + b0, l1 = g.acc[mf][nf][1] + b1;
            float h0 = g.acc[mf][nf][2] + b0, h1 = g.acc[mf][nf][3] + b1;
            if (act) { l0 = phi_act(l0); l1 = phi_act(l1);
                       h0 = phi_act(h0); h1 = phi_act(h1); }
            *(__half2*)(C + (size_t)m0 * 1024 + nc) =
                __half2(__float2half(l0), __float2half(l1));
            *(__half2*)(C + (size_t)(m0 + 8) * 1024 + nc) =
                __half2(__float2half(h0), __float2half(h1));
        }
    }
}

// ---------------------------------------------------------------------------
// Output GEMM: out = attn_fp16 @ Wo^T + bo  -> fp32
// ---------------------------------------------------------------------------
__global__ void __launch_bounds__(256, 2) gemm_out(
    const __half* __restrict__ A, const __half* __restrict__ W,
    const float* __restrict__ bias, float* __restrict__ C)
{
    extern __shared__ char smraw[];
    const int tid = threadIdx.x;
    const int wid = tid >> 5, lane = tid & 31;
    const int wm  = wid >> 2, wn = wid & 3;
    const int bm  = blockIdx.y, bn = blockIdx.x;

    GemmCore g;
    g.init(smem_u32(smraw), tid, A, W, bm, bn);
    g.run();

    #pragma unroll
    for (int mf = 0; mf < 4; mf++) {
        const int m0 = bm * 128 + wm * 64 + mf * 16 + (lane >> 2);
        #pragma unroll
        for (int nf = 0; nf < 4; nf++) {
            const int nc = bn * 128 + wn * 32 + nf * 8 + (lane & 3) * 2;
            const float b0 = __ldg(bias + nc), b1 = __ldg(bias + nc + 1);
            float2 lo, hi;
            lo.x = g.acc[mf][nf][0] + b0; lo.y = g.acc[mf][nf][1] + b1;
            hi.x = g.acc[mf][nf][2] + b0; hi.y = g.acc[mf][nf][3] + b1;
            *(float2*)(C + (size_t)m0 * 1024 + nc)       = lo;
            *(float2*)(C + (size_t)(m0 + 8) * 1024 + nc) = hi;
        }
    }
}

// ---------------------------------------------------------------------------
// fp32 -> fp16 convert, [rows, 1024]
// ---------------------------------------------------------------------------
__global__ __launch_bounds__(256) void conv_fp16(
    const float* __restrict__ src, __half* __restrict__ dst)
{
    const int m = blockIdx.x;
    const int c = threadIdx.x * 4;
    float4 v = *(const float4*)(src + (size_t)m * 1024 + c);
    __half2* d = (__half2*)(dst + (size_t)m * 1024 + c);
    d[0] = __half2(__float2half(v.x), __float2half(v.y));
    d[1] = __half2(__float2half(v.z), __float2half(v.w));
}

// ---------------------------------------------------------------------------
// KV summary (HMMA): per (b,h,split): kv[64,64] += k^T @ v over 512 t.
// Both k and v are [t, d] in smem -> trans ldmatrix for A and B fragments.
// 8 warps: 2 (m=dk) x 4 (n=dm); warp tile 32x16. grid (64, 8).
// ---------------------------------------------------------------------------
__global__ __launch_bounds__(256) void kv_hmma(
    const __half* __restrict__ k16, const __half* __restrict__ v16)
{
    // 4 stages x (k tile + v tile), each 32 rows x 144B
    __shared__ __align__(16) char sm[4 * 2 * 32 * RS64];
    const uint32_t smb = smem_u32(sm);
    const int tid = threadIdx.x, lane = tid & 31, wid = tid >> 5;
    const int wm = wid >> 2, wn = wid & 3;
    const int bh = blockIdx.x, b = bh >> 4, h = bh & 15;
    const int t0 = blockIdx.y * 512;
    static constexpr int NCH = 16;           // 16 chunks of 32 t
    static constexpr int STG = 2 * 32 * RS64; // stage bytes (9216)

    // load geometry: one 16B seg per tile per thread
    const int lrow = tid >> 3, lseg = tid & 7;
    const __half* gk = k16 + (size_t)(b * TT + t0 + lrow) * 1024 + h * 64 + lseg * 8;
    const __half* gv = v16 + (size_t)(b * TT + t0 + lrow) * 1024 + h * 64 + lseg * 8;
    const uint32_t sdst = (uint32_t)lrow * RS64 + lseg * 16;

    auto load_chunk = [&](int ch) {
        const uint32_t st = smb + (ch & 3) * STG;
        const size_t go = (size_t)ch * 32 * 1024;
        CP_ASYNC16(st + sdst,                  gk + go);
        CP_ASYNC16(st + 32 * RS64 + sdst,      gv + go);
        CP_COMMIT();
    };

    // trans-ldsm lane map: row k-idx, col m/n-idx
    const uint32_t trow = (lane & 7) + ((lane >> 4) & 1) * 8;
    const uint32_t tcol = ((lane >> 3) & 1) * 8;
    const uint32_t a_base = trow * RS64 + (wm * 32 + tcol) * 2;
    const uint32_t b_base = 32 * RS64 + trow * RS64 + (wn * 16 + tcol) * 2;

    float acc[2][2][4];
    #pragma unroll
    for (int i = 0; i < 2; i++)
        #pragma unroll
        for (int j = 0; j < 2; j++)
            #pragma unroll
            for (int r = 0; r < 4; r++) acc[i][j][r] = 0.0f;
    float ksacc = 0.0f;

    load_chunk(0); load_chunk(1); load_chunk(2);

    #pragma unroll 1
    for (int ch = 0; ch < NCH; ch++) {
        if (ch < NCH - 2)       cp_wait<2>();
        else if (ch == NCH - 2) cp_wait<1>();
        else                    cp_wait<0>();
        __syncthreads();
        if (ch + 3 < NCH) load_chunk(ch + 3);

        const uint32_t st = smb + (ch & 3) * STG;
        #pragma unroll
        for (int ks = 0; ks < 2; ks++) {  // two k16 steps per 32-t chunk
            const uint32_t ko = ks * 16 * RS64;
            uint32_t a[2][4], bfr[4];
            ldsm_x4_t(a[0], st + a_base + ko);
            ldsm_x4_t(a[1], st + a_base + ko + 16 * 2);
            ldsm_x4_t(bfr,  st + b_base + ko);
            #pragma unroll
            for (int mf = 0; mf < 2; mf++)
                #pragma unroll
                for (int nf = 0; nf < 2; nf++)
                    mma_fp16(acc[mf][nf], a[mf], bfr[nf], bfr[nf + 2]);
        }
        // ksum partial: warps 0,1 accumulate column sums of k tile
        if (tid < 64) {
            const __half* kc = (const __half*)(sm + (ch & 3) * STG);
            #pragma unroll
            for (int r = 0; r < 32; r++)
                ksacc += __half2float(*(const __half*)
                    ((const char*)kc + r * RS64 + tid * 2));
        }
    }

    float* kvb = g_kv + (size_t)bh * DKK * DKK;
    #pragma unroll
    for (int mf = 0; mf < 2; mf++) {
        const int row = wm * 32 + mf * 16 + (lane >> 2);
        #pragma unroll
        for (int nf = 0; nf < 2; nf++) {
            const int col = wn * 16 + nf * 8 + (lane & 3) * 2;
            atomicAdd(&kvb[row * 64 + col],           acc[mf][nf][0]);
            atomicAdd(&kvb[row * 64 + col + 1],       acc[mf][nf][1]);
            atomicAdd(&kvb[(row + 8) * 64 + col],     acc[mf][nf][2]);
            atomicAdd(&kvb[(row + 8) * 64 + col + 1], acc[mf][nf][3]);
        }
    }
    if (tid < 64) atomicAdd(&g_ksum[bh * 64 + tid], ksacc);
}

// ---------------------------------------------------------------------------
// kv fixup: f32 kv -> fp16 kv^T; kse = ksum + eps. grid 64.
// ---------------------------------------------------------------------------
__global__ __launch_bounds__(256) void kv_fix()
{
    const int bh = blockIdx.x;
    const float* kv = g_kv + (size_t)bh * 4096;
    __half* kvT = g_kvT + (size_t)bh * 4096;
    for (int i = threadIdx.x; i < 4096; i += 256) {
        const int dm = i >> 6, dk = i & 63;
        kvT[i] = __float2half(kv[dk * 64 + dm]);
    }
    if (threadIdx.x < 64)
        g_kse[bh * 64 + threadIdx.x] = g_ksum[bh * 64 + threadIdx.x] + EPSV;
}

// ---------------------------------------------------------------------------
// Attention apply (HMMA): out[t,dm] = z[t] * (q[t,:] @ kv[:,dm]), fp16 out.
// A = q [t][dk] (normal ldsm), B = kvT [dm][dk] (normal ldsm).
// 8 warps: 4 (m=t) x 2 (n=dm); warp tile 32x32. grid (64, 32).
// ---------------------------------------------------------------------------
__global__ __launch_bounds__(256) void attn_hmma(
    const __half* __restrict__ q16, __half* __restrict__ out)
{
    __shared__ __align__(16) char smq[128 * RS64];
    __shared__ __align__(16) char smkv[64 * RS64];
    __shared__ float zs[128];
    __shared__ float kse[64];

    const uint32_t sq = smem_u32(smq), skv = smem_u32(smkv);
    const int tid = threadIdx.x, lane = tid & 31, wid = tid >> 5;
    const int wm = wid >> 1, wn = wid & 1;
    const int bh = blockIdx.x, b = bh >> 4, h = bh & 15;
    const int t0 = blockIdx.y * 128;

    // load q tile: 128 rows x 8 segs = 1024 segs; 4 per thread
    {
        const __half* gq = q16 + (size_t)(b * TT + t0) * 1024 + h * 64;
        #pragma unroll
        for (int i = 0; i < 4; i++) {
            const int s = i * 256 + tid;
            const int r = s >> 3, c = s & 7;
            CP_ASYNC16(sq + r * RS64 + c * 16, gq + (size_t)r * 1024 + c * 8);
        }
        // kvT tile: 64 rows x 8 segs = 512 segs; 2 per thread
        const __half* gkv = g_kvT + (size_t)bh * 4096;
        #pragma unroll
        for (int i = 0; i < 2; i++) {
            const int s = i * 256 + tid;
            const int r = s >> 3, c = s & 7;
            CP_ASYNC16(skv + r * RS64 + c * 16, gkv + r * 64 + c * 8);
        }
        CP_COMMIT();
    }
    if (tid < 64) kse[tid] = g_kse[bh * 64 + tid];
    cp_wait<0>();
    __syncthreads();

    if (tid < 128) {
        float s = EPSV;
        const char* qrow = smq + tid * RS64;
        #pragma unroll
        for (int d = 0; d < 64; d++)
            s = fmaf(__half2float(*(const __half*)(qrow + d * 2)), kse[d], s);
        zs[tid] = 1.0f / s;
    }
    __syncthreads();

    const uint32_t a_base = (uint32_t)(wm * 32 + (lane & 15)) * RS64 + (lane >> 4) * 16;
    const uint32_t b_base = (uint32_t)(wn * 32 + (lane & 15)) * RS64 + (lane >> 4) * 16;

    float acc[2][4][4];
    #pragma unroll
    for (int i = 0; i < 2; i++)
        #pragma unroll
        for (int j = 0; j < 4; j++)
            #pragma unroll
            for (int r = 0; r < 4; r++) acc[i][j][r] = 0.0f;

    #pragma unroll
    for (int ks = 0; ks < 4; ks++) {
        const uint32_t ko = ks * 32;  // 16 fp16 = 32 B
        uint32_t a[2][4], bl[2][4];
        ldsm_x4(a[0], sq + a_base + ko);
        ldsm_x4(a[1], sq + a_base + 16 * RS64 + ko);
        ldsm_x4(bl[0], skv + b_base + ko);
        ldsm_x4(bl[1], skv + b_base + 16 * RS64 + ko);
        #pragma unroll
        for (int mf = 0; mf < 2; mf++)
            #pragma unroll
            for (int nf = 0; nf < 4; nf++)
                mma_fp16(acc[mf][nf], a[mf],
                         bl[nf >> 1][nf & 1], bl[nf >> 1][(nf & 1) + 2]);
    }

    #pragma unroll
    for (int mf = 0; mf < 2; mf++) {
        const int row = wm * 32 + mf * 16 + (lane >> 2);
        const float z0 = zs[row], z1 = zs[row + 8];
        #pragma unroll
        for (int nf = 0; nf < 4; nf++) {
            const int col = wn * 32 + nf * 8 + (lane & 3) * 2;
            __half2* o0 = (__half2*)(out + (size_t)(b * TT + t0 + row) * 1024 + h * 64 + col);
            __half2* o1 = (__half2*)(out + (size_t)(b * TT + t0 + row + 8) * 1024 + h * 64 + col);
            *o0 = __half2(__float2half(acc[mf][nf][0] * z0),
                          __float2half(acc[mf][nf][1] * z0));
            *o1 = __half2(__float2half(acc[mf][nf][2] * z1),
                          __float2half(acc[mf][nf][3] * z1));
        }
    }
}

// ---------------------------------------------------------------------------
extern "C" void kernel_launch(void* const* d_in, const int* in_sizes, int n_in,
                              void* d_out, int out_size)
{
    const float* x  = (const float*)d_in[0];
    const float* Wq = (const float*)d_in[1];
    const float* bq = (const float*)d_in[2];
    const float* Wk = (const float*)d_in[3];
    const float* bk = (const float*)d_in[4];
    const float* Wv = (const float*)d_in[5];
    const float* bv = (const float*)d_in[6];
    const float* Wo = (const float*)d_in[7];
    const float* bo = (const float*)d_in[8];
    float* out = (float*)d_out;

    __half *xs, *as, *wqkv, *wos, *qp, *kp, *vp;
    float *kvp, *ksp;
    cudaGetSymbolAddress((void**)&xs,   g_xs);
    cudaGetSymbolAddress((void**)&as,   g_as);
    cudaGetSymbolAddress((void**)&wqkv, g_wqkv);
    cudaGetSymbolAddress((void**)&wos,  g_wos);
    cudaGetSymbolAddress((void**)&qp,   g_q16);
    cudaGetSymbolAddress((void**)&kp,   g_k16);
    cudaGetSymbolAddress((void**)&vp,   g_v16);
    cudaGetSymbolAddress((void**)&kvp,  g_kv);
    cudaGetSymbolAddress((void**)&ksp,  g_ksum);

    cudaFuncSetAttribute(gemm_qkv, cudaFuncAttributeMaxDynamicSharedMemorySize, SMEM_GEMM);
    cudaFuncSetAttribute(gemm_out, cudaFuncAttributeMaxDynamicSharedMemorySize, SMEM_GEMM);

    cudaMemsetAsync(kvp, 0, sizeof(float) * BB * HH * DKK * DKK);
    cudaMemsetAsync(ksp, 0, sizeof(float) * BB * HH * DKK);

    conv_fp16<<<MT, 256>>>(x, xs);
    conv_fp16<<<DD, 256>>>(Wq, wqkv);
    conv_fp16<<<DD, 256>>>(Wk, wqkv + (size_t)DD * KK);
    conv_fp16<<<DD, 256>>>(Wv, wqkv + (size_t)2 * DD * KK);
    conv_fp16<<<DD, 256>>>(Wo, wos);

    gemm_qkv<<<dim3(24, MT / 128), 256, SMEM_GEMM>>>(
        xs, wqkv, bq, bk, bv, qp, kp, vp);

    kv_hmma<<<dim3(BB * HH, 8), 256>>>(kp, vp);
    kv_fix<<<BB * HH, 256>>>();
    attn_hmma<<<dim3(BB * HH, TT / 128), 256>>>(qp, as);

    gemm_out<<<dim3(DD / 128, MT / 128), 256, SMEM_GEMM>>>(as, wos, bo, out);
}